// round 2
// baseline (speedup 1.0000x reference)
#include <cuda_runtime.h>
#include <cstddef>

// Problem constants
#define BB 2
#define TT 2048
#define CC 1024
#define HH 16
#define DD 64
#define NEGINF (-1e10f)

// Scratch (device globals — no allocation allowed)
__device__ float g_q[(size_t)BB * HH * TT * DD];   // [B,H,T,D]
__device__ float g_k[(size_t)BB * HH * TT * DD];
__device__ float g_v[(size_t)BB * HH * TT * DD];
__device__ float g_y[(size_t)BB * TT * CC];        // [B,T,C] attention output

// ---------------------------------------------------------------------------
// Tiled SGEMM: C[M,N] = A[M,K] @ W[K,N] + bias[N]
// BM=BN=128, BK=8, 256 threads, 8x8 per-thread tile.
// mode 0: scatter epilogue into g_q/g_k/g_v ([B,H,T,D] layout)
// mode 1: plain row-major store into Cout
// A == nullptr means "read from g_y" (proj GEMM input).
// ---------------------------------------------------------------------------
__global__ __launch_bounds__(256) void sgemm_kernel(
    const float* __restrict__ A, const float* __restrict__ W,
    const float* __restrict__ bias, float* __restrict__ Cout,
    int M, int N, int K, int mode)
{
    if (A == nullptr) A = g_y;

    __shared__ __align__(16) float As[8][128];
    __shared__ __align__(16) float Bs[8][128];

    const int tid = threadIdx.x;
    const int m0 = blockIdx.y * 128;
    const int n0 = blockIdx.x * 128;

    // A tile load: 128 rows x 8 cols -> each thread one float4
    const int aRow = tid >> 1;
    const int aCol = (tid & 1) * 4;
    // B tile load: 8 rows x 128 cols -> each thread one float4
    const int bRow = tid >> 5;
    const int bCol = (tid & 31) * 4;

    const int tr = (tid >> 4) * 8;   // 0..120
    const int tc = (tid & 15) * 8;   // 0..120

    float acc[8][8];
#pragma unroll
    for (int i = 0; i < 8; i++)
#pragma unroll
        for (int j = 0; j < 8; j++) acc[i][j] = 0.0f;

    const float* Aptr = A + (size_t)(m0 + aRow) * K + aCol;
    const float* Bptr = W + (size_t)bRow * N + n0 + bCol;

    for (int k0 = 0; k0 < K; k0 += 8) {
        float4 av = *(const float4*)(Aptr + k0);
        As[aCol + 0][aRow] = av.x;
        As[aCol + 1][aRow] = av.y;
        As[aCol + 2][aRow] = av.z;
        As[aCol + 3][aRow] = av.w;
        float4 bv = *(const float4*)(Bptr + (size_t)k0 * N);
        *(float4*)&Bs[bRow][bCol] = bv;
        __syncthreads();

#pragma unroll
        for (int kk = 0; kk < 8; kk++) {
            float4 a0 = *(const float4*)&As[kk][tr];
            float4 a1 = *(const float4*)&As[kk][tr + 4];
            float4 b0 = *(const float4*)&Bs[kk][tc];
            float4 b1 = *(const float4*)&Bs[kk][tc + 4];
            float ra[8] = {a0.x, a0.y, a0.z, a0.w, a1.x, a1.y, a1.z, a1.w};
            float rb[8] = {b0.x, b0.y, b0.z, b0.w, b1.x, b1.y, b1.z, b1.w};
#pragma unroll
            for (int i = 0; i < 8; i++)
#pragma unroll
                for (int j = 0; j < 8; j++)
                    acc[i][j] += ra[i] * rb[j];
        }
        __syncthreads();
    }

    if (mode == 0) {
        // scatter into q/k/v [B,H,T,D]
#pragma unroll
        for (int i = 0; i < 8; i++) {
            const int m = m0 + tr + i;
            const int b = m >> 11;        // m / 2048
            const int t = m & 2047;
#pragma unroll
            for (int j = 0; j < 8; j++) {
                const int n = n0 + tc + j;
                float v = acc[i][j] + bias[n];
                const int region = n >> 10;        // 0=q 1=k 2=v
                const int c = n & 1023;
                const int h = c >> 6;
                const int dd = c & 63;
                float* dst = (region == 0) ? g_q : (region == 1) ? g_k : g_v;
                dst[((((size_t)b * HH + h) * TT) + t) * DD + dd] = v;
            }
        }
    } else {
#pragma unroll
        for (int i = 0; i < 8; i++) {
            const int m = m0 + tr + i;
#pragma unroll
            for (int j = 0; j < 8; j++) {
                const int n = n0 + tc + j;
                Cout[(size_t)m * N + n] = acc[i][j] + bias[n];
            }
        }
    }
}

// ---------------------------------------------------------------------------
// Flash attention (fp32, online softmax).
// Grid: (T/64, B*H). Block: 64 threads, thread-per-query.
// Causal tile skipping: block qt only visits kt <= qt.
// Dynamic smem: Ks(16K) + Vs(16K) + Ss(16K) + amS(256) = 49408 B > 48K static.
// ---------------------------------------------------------------------------
#define ATTN_SMEM_BYTES (3 * 64 * 64 * 4 + 64 * 4)

__global__ __launch_bounds__(64) void attn_kernel(const float* __restrict__ am)
{
    extern __shared__ __align__(16) float smem[];
    float* Ks  = smem;                 // 64*64
    float* Vs  = smem + 64 * 64;       // 64*64
    float* Ss  = smem + 2 * 64 * 64;   // 64*64
    float* amS = smem + 3 * 64 * 64;   // 64

    const int tid = threadIdx.x;
    const int bh = blockIdx.y;
    const int b = bh >> 4;
    const int h = bh & 15;
    const int q0 = blockIdx.x << 6;
    const int q = q0 + tid;

    const float* Qp = g_q + ((size_t)bh * TT + q) * DD;
    const float* Kbase = g_k + (size_t)bh * TT * DD;
    const float* Vbase = g_v + (size_t)bh * TT * DD;

    float qreg[64];
#pragma unroll
    for (int d = 0; d < 64; d += 4) {
        float4 t4 = *(const float4*)(Qp + d);
        qreg[d] = t4.x; qreg[d + 1] = t4.y; qreg[d + 2] = t4.z; qreg[d + 3] = t4.w;
    }
    float acc[64];
#pragma unroll
    for (int d = 0; d < 64; d++) acc[d] = 0.0f;

    float mrun = -3.0e38f;
    float l = 0.0f;

    const int nT = blockIdx.x + 1;
    for (int kt = 0; kt < nT; kt++) {
        const int k0 = kt << 6;

        // cooperative load of 64x64 K and V tiles (contiguous, float4)
        const float4* kg = (const float4*)(Kbase + (size_t)k0 * DD);
        const float4* vg = (const float4*)(Vbase + (size_t)k0 * DD);
        float4* ks4 = (float4*)Ks;
        float4* vs4 = (float4*)Vs;
#pragma unroll
        for (int i = 0; i < 16; i++) {
            ks4[tid + i * 64] = kg[tid + i * 64];
            vs4[tid + i * 64] = vg[tid + i * 64];
        }
        amS[tid] = am[b * TT + k0 + tid];
        __syncthreads();

        // pass 1: scores + tile max
        float tmax = -3.0e38f;
        for (int j = 0; j < 64; j++) {
            const float* kr = Ks + (j << 6);
            float s = 0.0f;
#pragma unroll
            for (int d = 0; d < 64; d++) s += qreg[d] * kr[d];
            s *= 0.125f;                       // 1/sqrt(64)
            s += amS[j] * NEGINF;              // padding mask
            if (k0 + j > q) s += NEGINF;       // causal mask
            Ss[(j << 6) + tid] = s;
            tmax = fmaxf(tmax, s);
        }

        const float mnew = fmaxf(mrun, tmax);
        const float corr = __expf(mrun - mnew);
        l *= corr;
#pragma unroll
        for (int d = 0; d < 64; d++) acc[d] *= corr;
        mrun = mnew;

        // pass 2: probs + PV accumulation
        for (int j = 0; j < 64; j++) {
            const float p = __expf(Ss[(j << 6) + tid] - mnew);
            l += p;
            const float* vr = Vs + (j << 6);
#pragma unroll
            for (int d = 0; d < 64; d++) acc[d] += p * vr[d];
        }
        __syncthreads();
    }

    const float inv = 1.0f / l;
    float* yp = g_y + ((size_t)(b * TT + q)) * CC + h * DD;
#pragma unroll
    for (int d = 0; d < 64; d += 4) {
        float4 o;
        o.x = acc[d] * inv; o.y = acc[d + 1] * inv;
        o.z = acc[d + 2] * inv; o.w = acc[d + 3] * inv;
        *(float4*)(yp + d) = o;
    }
}

// ---------------------------------------------------------------------------
extern "C" void kernel_launch(void* const* d_in, const int* in_sizes, int n_in,
                              void* d_out, int out_size)
{
    (void)in_sizes; (void)n_in; (void)out_size;
    const float* x  = (const float*)d_in[0];   // [B,T,C]
    const float* am = (const float*)d_in[1];   // [B,T]
    const float* Wa = (const float*)d_in[2];   // [C,3C]
    const float* ba = (const float*)d_in[3];   // [3C]
    const float* Wp = (const float*)d_in[4];   // [C,C]
    const float* bp = (const float*)d_in[5];   // [C]
    float* out = (float*)d_out;                // [B,T,C]

    // Opt-in to >48KB dynamic smem for the attention kernel (idempotent,
    // host-side attribute set — not an allocation, graph-capture safe).
    cudaFuncSetAttribute(attn_kernel,
                         cudaFuncAttributeMaxDynamicSharedMemorySize,
                         ATTN_SMEM_BYTES);

    // 1) QKV projection, scatter to [B,H,T,D]
    sgemm_kernel<<<dim3((3 * CC) / 128, (BB * TT) / 128), 256>>>(
        x, Wa, ba, nullptr, BB * TT, 3 * CC, CC, 0);

    // 2) flash attention -> g_y [B,T,C]
    attn_kernel<<<dim3(TT / 64, BB * HH), 64, ATTN_SMEM_BYTES>>>(am);

    // 3) output projection (A=nullptr -> read g_y)
    sgemm_kernel<<<dim3(CC / 128, (BB * TT) / 128), 256>>>(
        nullptr, Wp, bp, out, BB * TT, CC, CC, 1);
}

// round 4
// speedup vs baseline: 1.4364x; 1.4364x over previous
#include <cuda_runtime.h>
#include <cuda_bf16.h>
#include <cstdint>
#include <cstddef>

// Problem constants
#define BB 2
#define TT 2048
#define CC 1024
#define HH 16
#define DD 64
#define NEGINF (-1e10f)

// ---------------------------------------------------------------------------
// Device-global scratch (no allocation allowed)
// ---------------------------------------------------------------------------
__device__ float g_q[(size_t)BB * HH * TT * DD];   // [B,H,T,D]
__device__ float g_k[(size_t)BB * HH * TT * DD];
__device__ float g_v[(size_t)BB * HH * TT * DD];
__device__ float g_y[(size_t)BB * TT * CC];        // [B,T,C] attention output

// bf16 split operands for tensor-core GEMMs
__device__ __nv_bfloat16 g_xh[(size_t)BB * TT * CC];        // x hi   [M,K]
__device__ __nv_bfloat16 g_xl[(size_t)BB * TT * CC];        // x lo
__device__ __nv_bfloat16 g_yh[(size_t)BB * TT * CC];        // y hi   [M,K]
__device__ __nv_bfloat16 g_yl[(size_t)BB * TT * CC];
__device__ __nv_bfloat16 g_wah[(size_t)3 * CC * CC];        // W_attn^T hi [N=3C,K=C]
__device__ __nv_bfloat16 g_wal[(size_t)3 * CC * CC];
__device__ __nv_bfloat16 g_wph[(size_t)CC * CC];            // W_proj^T hi [N=C,K=C]
__device__ __nv_bfloat16 g_wpl[(size_t)CC * CC];

// ---------------------------------------------------------------------------
// mma.sync helpers (sm_80+ PTX — legal on plain sm_100 target)
// ---------------------------------------------------------------------------
__device__ __forceinline__ uint32_t smem_u32(const void* p) {
    return (uint32_t)__cvta_generic_to_shared(p);
}

__device__ __forceinline__ void ldmatrix_x4(uint32_t* r, uint32_t addr) {
    asm volatile("ldmatrix.sync.aligned.m8n8.x4.shared.b16 {%0,%1,%2,%3}, [%4];"
                 : "=r"(r[0]), "=r"(r[1]), "=r"(r[2]), "=r"(r[3]) : "r"(addr));
}
__device__ __forceinline__ void ldmatrix_x2(uint32_t* r, uint32_t addr) {
    asm volatile("ldmatrix.sync.aligned.m8n8.x2.shared.b16 {%0,%1}, [%2];"
                 : "=r"(r[0]), "=r"(r[1]) : "r"(addr));
}
__device__ __forceinline__ void mma_bf16(float* d, const uint32_t* a,
                                         const uint32_t* b) {
    asm volatile(
        "mma.sync.aligned.m16n8k16.row.col.f32.bf16.bf16.f32 "
        "{%0,%1,%2,%3}, {%4,%5,%6,%7}, {%8,%9}, {%0,%1,%2,%3};"
        : "+f"(d[0]), "+f"(d[1]), "+f"(d[2]), "+f"(d[3])
        : "r"(a[0]), "r"(a[1]), "r"(a[2]), "r"(a[3]), "r"(b[0]), "r"(b[1]));
}

// ---------------------------------------------------------------------------
// Convert kernels: fp32 -> (bf16 hi, bf16 lo)
// ---------------------------------------------------------------------------
__global__ void split_kernel(const float* __restrict__ src,
                             __nv_bfloat16* __restrict__ hi,
                             __nv_bfloat16* __restrict__ lo, int n)
{
    int i = blockIdx.x * blockDim.x + threadIdx.x;
    if (i < n) {
        float v = src[i];
        __nv_bfloat16 h = __float2bfloat16(v);
        hi[i] = h;
        lo[i] = __float2bfloat16(v - __bfloat162float(h));
    }
}

// src [K,N] row-major -> out [N,K] (transposed) split into hi/lo
__global__ void transpose_split_kernel(const float* __restrict__ src,
                                       __nv_bfloat16* __restrict__ hi,
                                       __nv_bfloat16* __restrict__ lo,
                                       int K, int N)
{
    __shared__ float tile[32][33];
    const int k0 = blockIdx.y * 32;
    const int n0 = blockIdx.x * 32;
    const int tx = threadIdx.x, ty = threadIdx.y;  // (32, 8)
#pragma unroll
    for (int i = ty; i < 32; i += 8)
        tile[i][tx] = src[(size_t)(k0 + i) * N + n0 + tx];
    __syncthreads();
#pragma unroll
    for (int i = ty; i < 32; i += 8) {
        float v = tile[tx][i];                    // src[k0+tx][n0+i]
        __nv_bfloat16 h = __float2bfloat16(v);
        size_t o = (size_t)(n0 + i) * K + k0 + tx;
        hi[o] = h;
        lo[o] = __float2bfloat16(v - __bfloat162float(h));
    }
}

// ---------------------------------------------------------------------------
// mma.sync bf16 3-pass GEMM: D[M,N] = A[M,K] @ B^T[N,K] + bias
// CTA tile 128x128, BK=32, 8 warps (2x4), warp tile 64x32 (4x4 m16n8k16).
// Smem rows padded to 40 elements (80B) -> conflict-free ldmatrix.
// mode 0: scatter into g_q/g_k/g_v;  mode 1: row-major store into Cout.
// ---------------------------------------------------------------------------
#define BK 32
#define LDS_ROW 40   // 32 + 8 pad elements (80 bytes/row)

__global__ __launch_bounds__(256) void tc_gemm_kernel(
    const __nv_bfloat16* __restrict__ Ahi, const __nv_bfloat16* __restrict__ Alo,
    const __nv_bfloat16* __restrict__ Bhi, const __nv_bfloat16* __restrict__ Blo,
    const float* __restrict__ bias, float* __restrict__ Cout,
    int N, int mode)
{
    __shared__ __align__(16) __nv_bfloat16 sAhi[128 * LDS_ROW];
    __shared__ __align__(16) __nv_bfloat16 sAlo[128 * LDS_ROW];
    __shared__ __align__(16) __nv_bfloat16 sBhi[128 * LDS_ROW];
    __shared__ __align__(16) __nv_bfloat16 sBlo[128 * LDS_ROW];

    const int tid = threadIdx.x;
    const int warp = tid >> 5;
    const int lane = tid & 31;
    const int warpM = warp >> 2;        // 0..1
    const int warpN = warp & 3;         // 0..3
    const int m0 = blockIdx.y * 128;
    const int n0 = blockIdx.x * 128;
    const int K = CC;                   // 1024

    float acc[4][4][4];
#pragma unroll
    for (int mt = 0; mt < 4; mt++)
#pragma unroll
        for (int nt = 0; nt < 4; nt++)
#pragma unroll
            for (int i = 0; i < 4; i++) acc[mt][nt][i] = 0.0f;

    // ldmatrix source addresses (per lane)
    const int aRow = warpM * 64 + (lane & 15);        // + mt*16
    const int aK   = (lane >> 4) * 8;                 // + ks*16
    const int bRow = warpN * 32 + (lane & 7);         // + nt*8
    const int bK   = ((lane >> 3) & 1) * 8;           // + ks*16

    const uint32_t sa_hi = smem_u32(sAhi), sa_lo = smem_u32(sAlo);
    const uint32_t sb_hi = smem_u32(sBhi), sb_lo = smem_u32(sBlo);

    for (int k0 = 0; k0 < K; k0 += BK) {
        // cooperative loads: 4 buffers, each 128 rows x 32 bf16 (4x16B per row)
#pragma unroll
        for (int sub = 0; sub < 2; sub++) {
            const int idx = sub * 256 + tid;   // 0..511
            const int r = idx >> 2;
            const int c = (idx & 3) * 8;       // element offset
            const size_t goA = (size_t)(m0 + r) * K + k0 + c;
            const size_t goB = (size_t)(n0 + r) * K + k0 + c;
            const int so = r * LDS_ROW + c;
            *(uint4*)(sAhi + so) = *(const uint4*)(Ahi + goA);
            *(uint4*)(sAlo + so) = *(const uint4*)(Alo + goA);
            *(uint4*)(sBhi + so) = *(const uint4*)(Bhi + goB);
            *(uint4*)(sBlo + so) = *(const uint4*)(Blo + goB);
        }
        __syncthreads();

        // 3 compensation passes: (Ahi,Bhi), (Ahi,Blo), (Alo,Bhi)
#pragma unroll
        for (int pass = 0; pass < 3; pass++) {
            const uint32_t aBase = (pass == 2) ? sa_lo : sa_hi;
            const uint32_t bBase = (pass == 1) ? sb_lo : sb_hi;
#pragma unroll
            for (int ks = 0; ks < 2; ks++) {
                const int kk = ks * 16;
                uint32_t af[4][4], bf[4][2];
#pragma unroll
                for (int mt = 0; mt < 4; mt++)
                    ldmatrix_x4(af[mt], aBase +
                        ((aRow + mt * 16) * LDS_ROW + aK + kk) * 2);
#pragma unroll
                for (int nt = 0; nt < 4; nt++)
                    ldmatrix_x2(bf[nt], bBase +
                        ((bRow + nt * 8) * LDS_ROW + bK + kk) * 2);
#pragma unroll
                for (int mt = 0; mt < 4; mt++)
#pragma unroll
                    for (int nt = 0; nt < 4; nt++)
                        mma_bf16(acc[mt][nt], af[mt], bf[nt]);
            }
        }
        __syncthreads();
    }

    // epilogue: d fragment -> (m, n), (m, n+1), (m+8, n), (m+8, n+1)
#pragma unroll
    for (int mt = 0; mt < 4; mt++) {
#pragma unroll
        for (int i = 0; i < 2; i++) {       // row half of the d fragment
            const int m = m0 + warpM * 64 + mt * 16 + (lane >> 2) + i * 8;
            const int b = m >> 11;
            const int t = m & 2047;
#pragma unroll
            for (int nt = 0; nt < 4; nt++) {
#pragma unroll
                for (int j = 0; j < 2; j++) {
                    const int n = n0 + warpN * 32 + nt * 8 + (lane & 3) * 2 + j;
                    const float v = acc[mt][nt][i * 2 + j] + bias[n];
                    if (mode == 0) {
                        const int region = n >> 10;      // 0=q 1=k 2=v
                        const int cc = n & 1023;
                        const int h = cc >> 6;
                        const int dd = cc & 63;
                        float* dst = (region == 0) ? g_q
                                   : (region == 1) ? g_k : g_v;
                        dst[(((size_t)b * HH + h) * TT + t) * DD + dd] = v;
                    } else {
                        Cout[(size_t)m * N + n] = v;
                    }
                }
            }
        }
    }
}

// ---------------------------------------------------------------------------
// Flash attention (fp32, online softmax) — unchanged from passing round.
// Grid: (T/64, B*H). Block: 64 threads, thread-per-query.
// ---------------------------------------------------------------------------
#define ATTN_SMEM_BYTES (3 * 64 * 64 * 4 + 64 * 4)

__global__ __launch_bounds__(64) void attn_kernel(const float* __restrict__ am)
{
    extern __shared__ __align__(16) float asm_smem[];
    float* Ks  = asm_smem;
    float* Vs  = asm_smem + 64 * 64;
    float* Ss  = asm_smem + 2 * 64 * 64;
    float* amS = asm_smem + 3 * 64 * 64;

    const int tid = threadIdx.x;
    const int bh = blockIdx.y;
    const int b = bh >> 4;
    const int h = bh & 15;
    const int q0 = blockIdx.x << 6;
    const int q = q0 + tid;

    const float* Qp = g_q + ((size_t)bh * TT + q) * DD;
    const float* Kbase = g_k + (size_t)bh * TT * DD;
    const float* Vbase = g_v + (size_t)bh * TT * DD;

    float qreg[64];
#pragma unroll
    for (int d = 0; d < 64; d += 4) {
        float4 t4 = *(const float4*)(Qp + d);
        qreg[d] = t4.x; qreg[d + 1] = t4.y; qreg[d + 2] = t4.z; qreg[d + 3] = t4.w;
    }
    float acc[64];
#pragma unroll
    for (int d = 0; d < 64; d++) acc[d] = 0.0f;

    float mrun = -3.0e38f;
    float l = 0.0f;

    const int nT = blockIdx.x + 1;
    for (int kt = 0; kt < nT; kt++) {
        const int k0 = kt << 6;
        const float4* kg = (const float4*)(Kbase + (size_t)k0 * DD);
        const float4* vg = (const float4*)(Vbase + (size_t)k0 * DD);
        float4* ks4 = (float4*)Ks;
        float4* vs4 = (float4*)Vs;
#pragma unroll
        for (int i = 0; i < 16; i++) {
            ks4[tid + i * 64] = kg[tid + i * 64];
            vs4[tid + i * 64] = vg[tid + i * 64];
        }
        amS[tid] = am[b * TT + k0 + tid];
        __syncthreads();

        float tmax = -3.0e38f;
        for (int j = 0; j < 64; j++) {
            const float* kr = Ks + (j << 6);
            float s = 0.0f;
#pragma unroll
            for (int d = 0; d < 64; d++) s += qreg[d] * kr[d];
            s *= 0.125f;
            s += amS[j] * NEGINF;
            if (k0 + j > q) s += NEGINF;
            Ss[(j << 6) + tid] = s;
            tmax = fmaxf(tmax, s);
        }

        const float mnew = fmaxf(mrun, tmax);
        const float corr = __expf(mrun - mnew);
        l *= corr;
#pragma unroll
        for (int d = 0; d < 64; d++) acc[d] *= corr;
        mrun = mnew;

        for (int j = 0; j < 64; j++) {
            const float p = __expf(Ss[(j << 6) + tid] - mnew);
            l += p;
            const float* vr = Vs + (j << 6);
#pragma unroll
            for (int d = 0; d < 64; d++) acc[d] += p * vr[d];
        }
        __syncthreads();
    }

    const float inv = 1.0f / l;
    float* yp = g_y + ((size_t)(b * TT + q)) * CC + h * DD;
#pragma unroll
    for (int d = 0; d < 64; d += 4) {
        float4 o;
        o.x = acc[d] * inv; o.y = acc[d + 1] * inv;
        o.z = acc[d + 2] * inv; o.w = acc[d + 3] * inv;
        *(float4*)(yp + d) = o;
    }
}

// ---------------------------------------------------------------------------
extern "C" void kernel_launch(void* const* d_in, const int* in_sizes, int n_in,
                              void* d_out, int out_size)
{
    (void)in_sizes; (void)n_in; (void)out_size;
    const float* x  = (const float*)d_in[0];   // [B,T,C]
    const float* am = (const float*)d_in[1];   // [B,T]
    const float* Wa = (const float*)d_in[2];   // [C,3C]
    const float* ba = (const float*)d_in[3];   // [3C]
    const float* Wp = (const float*)d_in[4];   // [C,C]
    const float* bp = (const float*)d_in[5];   // [C]
    float* out = (float*)d_out;                // [B,T,C]

    cudaFuncSetAttribute(attn_kernel,
                         cudaFuncAttributeMaxDynamicSharedMemorySize,
                         ATTN_SMEM_BYTES);

    // device-symbol addresses (host side)
    __nv_bfloat16 *xh, *xl, *yh, *yl, *wah, *wal, *wph, *wpl;
    cudaGetSymbolAddress((void**)&xh,  g_xh);
    cudaGetSymbolAddress((void**)&xl,  g_xl);
    cudaGetSymbolAddress((void**)&yh,  g_yh);
    cudaGetSymbolAddress((void**)&yl,  g_yl);
    cudaGetSymbolAddress((void**)&wah, g_wah);
    cudaGetSymbolAddress((void**)&wal, g_wal);
    cudaGetSymbolAddress((void**)&wph, g_wph);
    cudaGetSymbolAddress((void**)&wpl, g_wpl);
    float* yf;
    cudaGetSymbolAddress((void**)&yf, g_y);

    const int M = BB * TT;          // 4096

    // 0) operand conversion
    split_kernel<<<(M * CC) / 256, 256>>>(x, xh, xl, M * CC);
    transpose_split_kernel<<<dim3(3 * CC / 32, CC / 32), dim3(32, 8)>>>(
        Wa, wah, wal, CC, 3 * CC);
    transpose_split_kernel<<<dim3(CC / 32, CC / 32), dim3(32, 8)>>>(
        Wp, wph, wpl, CC, CC);

    // 1) QKV projection (mma.sync bf16 3-pass), scatter into [B,H,T,D]
    tc_gemm_kernel<<<dim3(3 * CC / 128, M / 128), 256>>>(
        xh, xl, wah, wal, ba, nullptr, 3 * CC, 0);

    // 2) flash attention -> g_y [B,T,C]
    attn_kernel<<<dim3(TT / 64, BB * HH), 64, ATTN_SMEM_BYTES>>>(am);

    // 3) split attention output, then output projection
    split_kernel<<<(M * CC) / 256, 256>>>(yf, yh, yl, M * CC);
    tc_gemm_kernel<<<dim3(CC / 128, M / 128), 256>>>(
        yh, yl, wph, wpl, bp, out, CC, 1);
}

// round 5
// speedup vs baseline: 2.9772x; 2.0726x over previous
#include <cuda_runtime.h>
#include <cuda_bf16.h>
#include <cstdint>
#include <cstddef>

// Problem constants
#define BB 2
#define TT 2048
#define CC 1024
#define HH 16
#define DD 64
#define NEGINF (-1e10f)

// ---------------------------------------------------------------------------
// Device-global scratch (no allocation allowed)
// ---------------------------------------------------------------------------
__device__ float g_q[(size_t)BB * HH * TT * DD];   // [B,H,T,D]
__device__ float g_k[(size_t)BB * HH * TT * DD];
__device__ float g_v[(size_t)BB * HH * TT * DD];
__device__ float g_y[(size_t)BB * TT * CC];        // [B,T,C] attention output

// bf16 split operands for tensor-core GEMMs
__device__ __nv_bfloat16 g_xh[(size_t)BB * TT * CC];
__device__ __nv_bfloat16 g_xl[(size_t)BB * TT * CC];
__device__ __nv_bfloat16 g_yh[(size_t)BB * TT * CC];
__device__ __nv_bfloat16 g_yl[(size_t)BB * TT * CC];
__device__ __nv_bfloat16 g_wah[(size_t)3 * CC * CC];
__device__ __nv_bfloat16 g_wal[(size_t)3 * CC * CC];
__device__ __nv_bfloat16 g_wph[(size_t)CC * CC];
__device__ __nv_bfloat16 g_wpl[(size_t)CC * CC];

// ---------------------------------------------------------------------------
// mma.sync helpers (sm_80+ PTX — legal on plain sm_100 target)
// ---------------------------------------------------------------------------
__device__ __forceinline__ uint32_t smem_u32(const void* p) {
    return (uint32_t)__cvta_generic_to_shared(p);
}

__device__ __forceinline__ void ldmatrix_x4(uint32_t* r, uint32_t addr) {
    asm volatile("ldmatrix.sync.aligned.m8n8.x4.shared.b16 {%0,%1,%2,%3}, [%4];"
                 : "=r"(r[0]), "=r"(r[1]), "=r"(r[2]), "=r"(r[3]) : "r"(addr));
}
__device__ __forceinline__ void ldmatrix_x4_trans(uint32_t* r, uint32_t addr) {
    asm volatile("ldmatrix.sync.aligned.m8n8.x4.trans.shared.b16 {%0,%1,%2,%3}, [%4];"
                 : "=r"(r[0]), "=r"(r[1]), "=r"(r[2]), "=r"(r[3]) : "r"(addr));
}
__device__ __forceinline__ void ldmatrix_x2(uint32_t* r, uint32_t addr) {
    asm volatile("ldmatrix.sync.aligned.m8n8.x2.shared.b16 {%0,%1}, [%2];"
                 : "=r"(r[0]), "=r"(r[1]) : "r"(addr));
}
__device__ __forceinline__ void mma_bf16(float* d, const uint32_t* a,
                                         const uint32_t* b) {
    asm volatile(
        "mma.sync.aligned.m16n8k16.row.col.f32.bf16.bf16.f32 "
        "{%0,%1,%2,%3}, {%4,%5,%6,%7}, {%8,%9}, {%0,%1,%2,%3};"
        : "+f"(d[0]), "+f"(d[1]), "+f"(d[2]), "+f"(d[3])
        : "r"(a[0]), "r"(a[1]), "r"(a[2]), "r"(a[3]), "r"(b[0]), "r"(b[1]));
}

// pack two f32 as bf16x2: low element = first arg
__device__ __forceinline__ uint32_t pack_bf16(float lo, float hi) {
    uint32_t r;
    asm("cvt.rn.bf16x2.f32 %0, %1, %2;" : "=r"(r) : "f"(hi), "f"(lo));
    return r;
}

// ---------------------------------------------------------------------------
// Convert kernels: fp32 -> (bf16 hi, bf16 lo)
// ---------------------------------------------------------------------------
__global__ void split_kernel(const float* __restrict__ src,
                             __nv_bfloat16* __restrict__ hi,
                             __nv_bfloat16* __restrict__ lo, int n)
{
    int i = blockIdx.x * blockDim.x + threadIdx.x;
    if (i < n) {
        float v = src[i];
        __nv_bfloat16 h = __float2bfloat16(v);
        hi[i] = h;
        lo[i] = __float2bfloat16(v - __bfloat162float(h));
    }
}

// src [K,N] row-major -> out [N,K] (transposed) split into hi/lo
__global__ void transpose_split_kernel(const float* __restrict__ src,
                                       __nv_bfloat16* __restrict__ hi,
                                       __nv_bfloat16* __restrict__ lo,
                                       int K, int N)
{
    __shared__ float tile[32][33];
    const int k0 = blockIdx.y * 32;
    const int n0 = blockIdx.x * 32;
    const int tx = threadIdx.x, ty = threadIdx.y;  // (32, 8)
#pragma unroll
    for (int i = ty; i < 32; i += 8)
        tile[i][tx] = src[(size_t)(k0 + i) * N + n0 + tx];
    __syncthreads();
#pragma unroll
    for (int i = ty; i < 32; i += 8) {
        float v = tile[tx][i];
        __nv_bfloat16 h = __float2bfloat16(v);
        size_t o = (size_t)(n0 + i) * K + k0 + tx;
        hi[o] = h;
        lo[o] = __float2bfloat16(v - __bfloat162float(h));
    }
}

// ---------------------------------------------------------------------------
// mma.sync bf16 3-pass GEMM (unchanged from passing Round 4)
// ---------------------------------------------------------------------------
#define BK 32
#define LDS_ROW 40

__global__ __launch_bounds__(256) void tc_gemm_kernel(
    const __nv_bfloat16* __restrict__ Ahi, const __nv_bfloat16* __restrict__ Alo,
    const __nv_bfloat16* __restrict__ Bhi, const __nv_bfloat16* __restrict__ Blo,
    const float* __restrict__ bias, float* __restrict__ Cout,
    int N, int mode)
{
    __shared__ __align__(16) __nv_bfloat16 sAhi[128 * LDS_ROW];
    __shared__ __align__(16) __nv_bfloat16 sAlo[128 * LDS_ROW];
    __shared__ __align__(16) __nv_bfloat16 sBhi[128 * LDS_ROW];
    __shared__ __align__(16) __nv_bfloat16 sBlo[128 * LDS_ROW];

    const int tid = threadIdx.x;
    const int warp = tid >> 5;
    const int lane = tid & 31;
    const int warpM = warp >> 2;
    const int warpN = warp & 3;
    const int m0 = blockIdx.y * 128;
    const int n0 = blockIdx.x * 128;
    const int K = CC;

    float acc[4][4][4];
#pragma unroll
    for (int mt = 0; mt < 4; mt++)
#pragma unroll
        for (int nt = 0; nt < 4; nt++)
#pragma unroll
            for (int i = 0; i < 4; i++) acc[mt][nt][i] = 0.0f;

    const int aRow = warpM * 64 + (lane & 15);
    const int aK   = (lane >> 4) * 8;
    const int bRow = warpN * 32 + (lane & 7);
    const int bK   = ((lane >> 3) & 1) * 8;

    const uint32_t sa_hi = smem_u32(sAhi), sa_lo = smem_u32(sAlo);
    const uint32_t sb_hi = smem_u32(sBhi), sb_lo = smem_u32(sBlo);

    for (int k0 = 0; k0 < K; k0 += BK) {
#pragma unroll
        for (int sub = 0; sub < 2; sub++) {
            const int idx = sub * 256 + tid;
            const int r = idx >> 2;
            const int c = (idx & 3) * 8;
            const size_t goA = (size_t)(m0 + r) * K + k0 + c;
            const size_t goB = (size_t)(n0 + r) * K + k0 + c;
            const int so = r * LDS_ROW + c;
            *(uint4*)(sAhi + so) = *(const uint4*)(Ahi + goA);
            *(uint4*)(sAlo + so) = *(const uint4*)(Alo + goA);
            *(uint4*)(sBhi + so) = *(const uint4*)(Bhi + goB);
            *(uint4*)(sBlo + so) = *(const uint4*)(Blo + goB);
        }
        __syncthreads();

#pragma unroll
        for (int pass = 0; pass < 3; pass++) {
            const uint32_t aBase = (pass == 2) ? sa_lo : sa_hi;
            const uint32_t bBase = (pass == 1) ? sb_lo : sb_hi;
#pragma unroll
            for (int ks = 0; ks < 2; ks++) {
                const int kk = ks * 16;
                uint32_t af[4][4], bf[4][2];
#pragma unroll
                for (int mt = 0; mt < 4; mt++)
                    ldmatrix_x4(af[mt], aBase +
                        ((aRow + mt * 16) * LDS_ROW + aK + kk) * 2);
#pragma unroll
                for (int nt = 0; nt < 4; nt++)
                    ldmatrix_x2(bf[nt], bBase +
                        ((bRow + nt * 8) * LDS_ROW + bK + kk) * 2);
#pragma unroll
                for (int mt = 0; mt < 4; mt++)
#pragma unroll
                    for (int nt = 0; nt < 4; nt++)
                        mma_bf16(acc[mt][nt], af[mt], bf[nt]);
            }
        }
        __syncthreads();
    }

#pragma unroll
    for (int mt = 0; mt < 4; mt++) {
#pragma unroll
        for (int i = 0; i < 2; i++) {
            const int m = m0 + warpM * 64 + mt * 16 + (lane >> 2) + i * 8;
            const int b = m >> 11;
            const int t = m & 2047;
#pragma unroll
            for (int nt = 0; nt < 4; nt++) {
#pragma unroll
                for (int j = 0; j < 2; j++) {
                    const int n = n0 + warpN * 32 + nt * 8 + (lane & 3) * 2 + j;
                    const float v = acc[mt][nt][i * 2 + j] + bias[n];
                    if (mode == 0) {
                        const int region = n >> 10;
                        const int cc = n & 1023;
                        const int h = cc >> 6;
                        const int dd = cc & 63;
                        float* dst = (region == 0) ? g_q
                                   : (region == 1) ? g_k : g_v;
                        dst[(((size_t)b * HH + h) * TT + t) * DD + dd] = v;
                    } else {
                        Cout[(size_t)m * N + n] = v;
                    }
                }
            }
        }
    }
}

// ---------------------------------------------------------------------------
// Tensor-core flash attention with hi/lo compensation on both MMAs.
// Grid: (T/128, B*H). Block: 256 threads (8 warps x 16 query rows).
// KV tiles of 64 staged in smem as bf16 hi/lo (72-elem padded rows).
// ---------------------------------------------------------------------------
#define KVROW 72   // 64 + 8 pad bf16 elems -> conflict-free ldmatrix

__global__ __launch_bounds__(256) void attn_tc_kernel(const float* __restrict__ am)
{
    __shared__ __align__(16) __nv_bfloat16 sKhi[64 * KVROW];
    __shared__ __align__(16) __nv_bfloat16 sKlo[64 * KVROW];
    __shared__ __align__(16) __nv_bfloat16 sVhi[64 * KVROW];
    __shared__ __align__(16) __nv_bfloat16 sVlo[64 * KVROW];
    __shared__ float amS[64];

    const int tid = threadIdx.x;
    const int warp = tid >> 5;
    const int lane = tid & 31;
    const int g = lane >> 2;        // row-in-8
    const int c = lane & 3;         // col group
    const int bh = blockIdx.y;
    const int b = bh >> 4;
    const int h = bh & 15;
    const int q0 = blockIdx.x * 128;

    const int r1 = q0 + warp * 16 + g;    // first fragment row
    const int r2 = r1 + 8;

    const float* Qb = g_q + (size_t)bh * TT * DD;
    const float* Kb = g_k + (size_t)bh * TT * DD;
    const float* Vb = g_v + (size_t)bh * TT * DD;

    // --- load & split Q fragments into registers (hi/lo), cached for all tiles
    uint32_t qh[4][4], ql[4][4];
#pragma unroll
    for (int ks = 0; ks < 4; ks++) {
#pragma unroll
        for (int half = 0; half < 2; half++) {      // k 0-7 / 8-15
            const int col = ks * 16 + half * 8 + c * 2;
            float2 v0 = *(const float2*)(Qb + (size_t)r1 * DD + col);
            float2 v1 = *(const float2*)(Qb + (size_t)r2 * DD + col);
            float h0x = __bfloat162float(__float2bfloat16(v0.x));
            float h0y = __bfloat162float(__float2bfloat16(v0.y));
            float h1x = __bfloat162float(__float2bfloat16(v1.x));
            float h1y = __bfloat162float(__float2bfloat16(v1.y));
            qh[ks][half * 2 + 0] = pack_bf16(v0.x, v0.y);
            qh[ks][half * 2 + 1] = pack_bf16(v1.x, v1.y);
            ql[ks][half * 2 + 0] = pack_bf16(v0.x - h0x, v0.y - h0y);
            ql[ks][half * 2 + 1] = pack_bf16(v1.x - h1x, v1.y - h1y);
        }
    }
    // reorder: a-frag order is {(r1,klo),(r2,klo),(r1,khi),(r2,khi)} — our fill
    // wrote [0]=r1klo [1]=r2klo [2]=r1khi [3]=r2khi. correct already.

    float o[8][4];
#pragma unroll
    for (int nt = 0; nt < 8; nt++)
#pragma unroll
        for (int i = 0; i < 4; i++) o[nt][i] = 0.0f;
    float m0v = -1e30f, m1v = -1e30f;
    float l0 = 0.0f, l1 = 0.0f;

    const uint32_t skh = smem_u32(sKhi), skl = smem_u32(sKlo);
    const uint32_t svh = smem_u32(sVhi), svl = smem_u32(sVlo);

    const int g4 = lane >> 3;       // ldmatrix address group
    const int l8 = lane & 7;

    const int nkv = 2 * (blockIdx.x + 1);
    for (int kt = 0; kt < nkv; kt++) {
        const int k0 = kt * 64;

        // --- stage K/V tile: fp32 -> bf16 hi/lo in smem
        {
            const int r = tid >> 2;
            const int cb = (tid & 3) * 16;
#pragma unroll
            for (int i = 0; i < 4; i++) {
                const int cc0 = cb + i * 4;
                float4 kv = *(const float4*)(Kb + (size_t)(k0 + r) * DD + cc0);
                float4 vv = *(const float4*)(Vb + (size_t)(k0 + r) * DD + cc0);
                float kx = __bfloat162float(__float2bfloat16(kv.x));
                float ky = __bfloat162float(__float2bfloat16(kv.y));
                float kz = __bfloat162float(__float2bfloat16(kv.z));
                float kw = __bfloat162float(__float2bfloat16(kv.w));
                float vx = __bfloat162float(__float2bfloat16(vv.x));
                float vy = __bfloat162float(__float2bfloat16(vv.y));
                float vz = __bfloat162float(__float2bfloat16(vv.z));
                float vw = __bfloat162float(__float2bfloat16(vv.w));
                uint32_t* p;
                p = (uint32_t*)(sKhi + r * KVROW + cc0);
                p[0] = pack_bf16(kv.x, kv.y); p[1] = pack_bf16(kv.z, kv.w);
                p = (uint32_t*)(sKlo + r * KVROW + cc0);
                p[0] = pack_bf16(kv.x - kx, kv.y - ky);
                p[1] = pack_bf16(kv.z - kz, kv.w - kw);
                p = (uint32_t*)(sVhi + r * KVROW + cc0);
                p[0] = pack_bf16(vv.x, vv.y); p[1] = pack_bf16(vv.z, vv.w);
                p = (uint32_t*)(sVlo + r * KVROW + cc0);
                p[0] = pack_bf16(vv.x - vx, vv.y - vy);
                p[1] = pack_bf16(vv.z - vz, vv.w - vw);
            }
            if (tid < 64) amS[tid] = am[b * TT + k0 + tid];
        }
        __syncthreads();

        // --- S = Q @ K^T (3-term compensation)
        float s[8][4];
#pragma unroll
        for (int nt = 0; nt < 8; nt++)
#pragma unroll
            for (int i = 0; i < 4; i++) s[nt][i] = 0.0f;

#pragma unroll
        for (int ks = 0; ks < 4; ks++) {
#pragma unroll
            for (int nt2 = 0; nt2 < 4; nt2++) {
                // K address: row = nt2*16 + (g4>>1)*8 + l8, col = ks*16 + (g4&1)*8
                const uint32_t off =
                    ((nt2 * 16 + (g4 >> 1) * 8 + l8) * KVROW +
                     ks * 16 + (g4 & 1) * 8) * 2;
                uint32_t bhf[4], blf[4];
                ldmatrix_x4(bhf, skh + off);
                ldmatrix_x4(blf, skl + off);
                mma_bf16(s[nt2 * 2 + 0], qh[ks], bhf);
                mma_bf16(s[nt2 * 2 + 1], qh[ks], bhf + 2);
                mma_bf16(s[nt2 * 2 + 0], qh[ks], blf);
                mma_bf16(s[nt2 * 2 + 1], qh[ks], blf + 2);
                mma_bf16(s[nt2 * 2 + 0], ql[ks], bhf);
                mma_bf16(s[nt2 * 2 + 1], ql[ks], bhf + 2);
            }
        }

        // --- scale + masks
#pragma unroll
        for (int nt = 0; nt < 8; nt++) {
            const int colb = nt * 8 + c * 2;
            const float a0 = amS[colb] * NEGINF;
            const float a1 = amS[colb + 1] * NEGINF;
            s[nt][0] = s[nt][0] * 0.125f + a0;
            s[nt][1] = s[nt][1] * 0.125f + a1;
            s[nt][2] = s[nt][2] * 0.125f + a0;
            s[nt][3] = s[nt][3] * 0.125f + a1;
            const int kg0 = k0 + colb;
            if (kg0 > r1)     s[nt][0] = -1e30f;
            if (kg0 + 1 > r1) s[nt][1] = -1e30f;
            if (kg0 > r2)     s[nt][2] = -1e30f;
            if (kg0 + 1 > r2) s[nt][3] = -1e30f;
        }

        // --- online softmax
        float t0 = -1e30f, t1 = -1e30f;
#pragma unroll
        for (int nt = 0; nt < 8; nt++) {
            t0 = fmaxf(t0, fmaxf(s[nt][0], s[nt][1]));
            t1 = fmaxf(t1, fmaxf(s[nt][2], s[nt][3]));
        }
        t0 = fmaxf(t0, __shfl_xor_sync(0xffffffffu, t0, 1));
        t0 = fmaxf(t0, __shfl_xor_sync(0xffffffffu, t0, 2));
        t1 = fmaxf(t1, __shfl_xor_sync(0xffffffffu, t1, 1));
        t1 = fmaxf(t1, __shfl_xor_sync(0xffffffffu, t1, 2));

        const float mn0 = fmaxf(m0v, t0);
        const float mn1 = fmaxf(m1v, t1);
        const float cr0 = __expf(m0v - mn0);
        const float cr1 = __expf(m1v - mn1);
        m0v = mn0; m1v = mn1;

        float s0 = 0.0f, s1 = 0.0f;
#pragma unroll
        for (int nt = 0; nt < 8; nt++) {
            s[nt][0] = __expf(s[nt][0] - mn0);
            s[nt][1] = __expf(s[nt][1] - mn0);
            s[nt][2] = __expf(s[nt][2] - mn1);
            s[nt][3] = __expf(s[nt][3] - mn1);
            s0 += s[nt][0] + s[nt][1];
            s1 += s[nt][2] + s[nt][3];
            o[nt][0] *= cr0; o[nt][1] *= cr0;
            o[nt][2] *= cr1; o[nt][3] *= cr1;
        }
        s0 += __shfl_xor_sync(0xffffffffu, s0, 1);
        s0 += __shfl_xor_sync(0xffffffffu, s0, 2);
        s1 += __shfl_xor_sync(0xffffffffu, s1, 1);
        s1 += __shfl_xor_sync(0xffffffffu, s1, 2);
        l0 = l0 * cr0 + s0;
        l1 = l1 * cr1 + s1;

        // --- O += P @ V (3-term compensation); P frags built per seq-kstep
#pragma unroll
        for (int j = 0; j < 4; j++) {
            uint32_t pfh[4], pfl[4];
            {
                const float p00 = s[2 * j][0],     p01 = s[2 * j][1];
                const float p10 = s[2 * j][2],     p11 = s[2 * j][3];
                const float p20 = s[2 * j + 1][0], p21 = s[2 * j + 1][1];
                const float p30 = s[2 * j + 1][2], p31 = s[2 * j + 1][3];
                const float h00 = __bfloat162float(__float2bfloat16(p00));
                const float h01 = __bfloat162float(__float2bfloat16(p01));
                const float h10 = __bfloat162float(__float2bfloat16(p10));
                const float h11 = __bfloat162float(__float2bfloat16(p11));
                const float h20 = __bfloat162float(__float2bfloat16(p20));
                const float h21 = __bfloat162float(__float2bfloat16(p21));
                const float h30 = __bfloat162float(__float2bfloat16(p30));
                const float h31 = __bfloat162float(__float2bfloat16(p31));
                pfh[0] = pack_bf16(p00, p01);
                pfh[1] = pack_bf16(p10, p11);
                pfh[2] = pack_bf16(p20, p21);
                pfh[3] = pack_bf16(p30, p31);
                pfl[0] = pack_bf16(p00 - h00, p01 - h01);
                pfl[1] = pack_bf16(p10 - h10, p11 - h11);
                pfl[2] = pack_bf16(p20 - h20, p21 - h21);
                pfl[3] = pack_bf16(p30 - h30, p31 - h31);
            }
#pragma unroll
            for (int nt2 = 0; nt2 < 4; nt2++) {
                // V address (trans): row(seq) = 16j + (g4&1)*8 + l8,
                //                    col(d)   = nt2*16 + (g4>>1)*8
                const uint32_t off =
                    ((16 * j + (g4 & 1) * 8 + l8) * KVROW +
                     nt2 * 16 + (g4 >> 1) * 8) * 2;
                uint32_t vhf[4], vlf[4];
                ldmatrix_x4_trans(vhf, svh + off);
                ldmatrix_x4_trans(vlf, svl + off);
                mma_bf16(o[nt2 * 2 + 0], pfh, vhf);
                mma_bf16(o[nt2 * 2 + 1], pfh, vhf + 2);
                mma_bf16(o[nt2 * 2 + 0], pfh, vlf);
                mma_bf16(o[nt2 * 2 + 1], pfh, vlf + 2);
                mma_bf16(o[nt2 * 2 + 0], pfl, vhf);
                mma_bf16(o[nt2 * 2 + 1], pfl, vhf + 2);
            }
        }
        __syncthreads();
    }

    // --- epilogue: normalize, write to g_y [B,T,C]
    const float i0 = 1.0f / l0;
    const float i1 = 1.0f / l1;
    float* y1 = g_y + ((size_t)(b * TT + r1)) * CC + h * DD;
    float* y2 = g_y + ((size_t)(b * TT + r2)) * CC + h * DD;
#pragma unroll
    for (int nt = 0; nt < 8; nt++) {
        const int col = nt * 8 + c * 2;
        float2 w0, w1;
        w0.x = o[nt][0] * i0; w0.y = o[nt][1] * i0;
        w1.x = o[nt][2] * i1; w1.y = o[nt][3] * i1;
        *(float2*)(y1 + col) = w0;
        *(float2*)(y2 + col) = w1;
    }
}

// ---------------------------------------------------------------------------
extern "C" void kernel_launch(void* const* d_in, const int* in_sizes, int n_in,
                              void* d_out, int out_size)
{
    (void)in_sizes; (void)n_in; (void)out_size;
    const float* x  = (const float*)d_in[0];   // [B,T,C]
    const float* am = (const float*)d_in[1];   // [B,T]
    const float* Wa = (const float*)d_in[2];   // [C,3C]
    const float* ba = (const float*)d_in[3];   // [3C]
    const float* Wp = (const float*)d_in[4];   // [C,C]
    const float* bp = (const float*)d_in[5];   // [C]
    float* out = (float*)d_out;                // [B,T,C]

    __nv_bfloat16 *xh, *xl, *yh, *yl, *wah, *wal, *wph, *wpl;
    cudaGetSymbolAddress((void**)&xh,  g_xh);
    cudaGetSymbolAddress((void**)&xl,  g_xl);
    cudaGetSymbolAddress((void**)&yh,  g_yh);
    cudaGetSymbolAddress((void**)&yl,  g_yl);
    cudaGetSymbolAddress((void**)&wah, g_wah);
    cudaGetSymbolAddress((void**)&wal, g_wal);
    cudaGetSymbolAddress((void**)&wph, g_wph);
    cudaGetSymbolAddress((void**)&wpl, g_wpl);
    float* yf;
    cudaGetSymbolAddress((void**)&yf, g_y);

    const int M = BB * TT;          // 4096

    // 0) operand conversion
    split_kernel<<<(M * CC) / 256, 256>>>(x, xh, xl, M * CC);
    transpose_split_kernel<<<dim3(3 * CC / 32, CC / 32), dim3(32, 8)>>>(
        Wa, wah, wal, CC, 3 * CC);
    transpose_split_kernel<<<dim3(CC / 32, CC / 32), dim3(32, 8)>>>(
        Wp, wph, wpl, CC, CC);

    // 1) QKV projection (mma.sync bf16 3-pass), scatter into [B,H,T,D]
    tc_gemm_kernel<<<dim3(3 * CC / 128, M / 128), 256>>>(
        xh, xl, wah, wal, ba, nullptr, 3 * CC, 0);

    // 2) tensor-core flash attention -> g_y [B,T,C]
    attn_tc_kernel<<<dim3(TT / 128, BB * HH), 256>>>(am);

    // 3) split attention output, then output projection
    split_kernel<<<(M * CC) / 256, 256>>>(yf, yh, yl, M * CC);
    tc_gemm_kernel<<<dim3(CC / 128, M / 128), 256>>>(
        yh, yl, wph, wpl, bp, out, CC, 1);
}

// round 6
// speedup vs baseline: 3.8095x; 1.2796x over previous
#include <cuda_runtime.h>
#include <cuda_bf16.h>
#include <cstdint>
#include <cstddef>

// Problem constants
#define BB 2
#define TT 2048
#define CC 1024
#define HH 16
#define DD 64
#define NEGINF (-1e10f)

// ---------------------------------------------------------------------------
// Device-global scratch (no allocation allowed). q/k/v/y live ONLY as
// pre-split bf16 hi/lo pairs (same total bytes as fp32).
// ---------------------------------------------------------------------------
__device__ __nv_bfloat16 g_qh[(size_t)BB * HH * TT * DD];
__device__ __nv_bfloat16 g_ql[(size_t)BB * HH * TT * DD];
__device__ __nv_bfloat16 g_kh[(size_t)BB * HH * TT * DD];
__device__ __nv_bfloat16 g_kl[(size_t)BB * HH * TT * DD];
__device__ __nv_bfloat16 g_vh[(size_t)BB * HH * TT * DD];
__device__ __nv_bfloat16 g_vl[(size_t)BB * HH * TT * DD];
__device__ __nv_bfloat16 g_yh[(size_t)BB * TT * CC];
__device__ __nv_bfloat16 g_yl[(size_t)BB * TT * CC];

__device__ __nv_bfloat16 g_xh[(size_t)BB * TT * CC];
__device__ __nv_bfloat16 g_xl[(size_t)BB * TT * CC];
__device__ __nv_bfloat16 g_wah[(size_t)3 * CC * CC];
__device__ __nv_bfloat16 g_wal[(size_t)3 * CC * CC];
__device__ __nv_bfloat16 g_wph[(size_t)CC * CC];
__device__ __nv_bfloat16 g_wpl[(size_t)CC * CC];

// ---------------------------------------------------------------------------
// PTX helpers (sm_80+ — legal on plain sm_100 target)
// ---------------------------------------------------------------------------
__device__ __forceinline__ uint32_t smem_u32(const void* p) {
    return (uint32_t)__cvta_generic_to_shared(p);
}
__device__ __forceinline__ void cp16(uint32_t s, const void* g) {
    asm volatile("cp.async.cg.shared.global [%0], [%1], 16;" :: "r"(s), "l"(g));
}
__device__ __forceinline__ void cp_commit() {
    asm volatile("cp.async.commit_group;" ::: "memory");
}
template <int N>
__device__ __forceinline__ void cp_wait() {
    asm volatile("cp.async.wait_group %0;" :: "n"(N) : "memory");
}
__device__ __forceinline__ void ldmatrix_x4(uint32_t* r, uint32_t addr) {
    asm volatile("ldmatrix.sync.aligned.m8n8.x4.shared.b16 {%0,%1,%2,%3}, [%4];"
                 : "=r"(r[0]), "=r"(r[1]), "=r"(r[2]), "=r"(r[3]) : "r"(addr));
}
__device__ __forceinline__ void ldmatrix_x4_trans(uint32_t* r, uint32_t addr) {
    asm volatile("ldmatrix.sync.aligned.m8n8.x4.trans.shared.b16 {%0,%1,%2,%3}, [%4];"
                 : "=r"(r[0]), "=r"(r[1]), "=r"(r[2]), "=r"(r[3]) : "r"(addr));
}
__device__ __forceinline__ void ldmatrix_x2(uint32_t* r, uint32_t addr) {
    asm volatile("ldmatrix.sync.aligned.m8n8.x2.shared.b16 {%0,%1}, [%2];"
                 : "=r"(r[0]), "=r"(r[1]) : "r"(addr));
}
__device__ __forceinline__ void mma_bf16(float* d, const uint32_t* a,
                                         const uint32_t* b) {
    asm volatile(
        "mma.sync.aligned.m16n8k16.row.col.f32.bf16.bf16.f32 "
        "{%0,%1,%2,%3}, {%4,%5,%6,%7}, {%8,%9}, {%0,%1,%2,%3};"
        : "+f"(d[0]), "+f"(d[1]), "+f"(d[2]), "+f"(d[3])
        : "r"(a[0]), "r"(a[1]), "r"(a[2]), "r"(a[3]), "r"(b[0]), "r"(b[1]));
}
// pack two f32 as bf16x2: first arg -> low half
__device__ __forceinline__ uint32_t pack_bf16(float lo, float hi) {
    uint32_t r;
    asm("cvt.rn.bf16x2.f32 %0, %1, %2;" : "=r"(r) : "f"(hi), "f"(lo));
    return r;
}

// ---------------------------------------------------------------------------
// Convert kernels: fp32 -> (bf16 hi, bf16 lo)
// ---------------------------------------------------------------------------
__global__ void split_kernel(const float* __restrict__ src,
                             __nv_bfloat16* __restrict__ hi,
                             __nv_bfloat16* __restrict__ lo, int n)
{
    int i = blockIdx.x * blockDim.x + threadIdx.x;
    if (i < n) {
        float v = src[i];
        __nv_bfloat16 h = __float2bfloat16(v);
        hi[i] = h;
        lo[i] = __float2bfloat16(v - __bfloat162float(h));
    }
}

__global__ void transpose_split_kernel(const float* __restrict__ src,
                                       __nv_bfloat16* __restrict__ hi,
                                       __nv_bfloat16* __restrict__ lo,
                                       int K, int N)
{
    __shared__ float tile[32][33];
    const int k0 = blockIdx.y * 32;
    const int n0 = blockIdx.x * 32;
    const int tx = threadIdx.x, ty = threadIdx.y;  // (32, 8)
#pragma unroll
    for (int i = ty; i < 32; i += 8)
        tile[i][tx] = src[(size_t)(k0 + i) * N + n0 + tx];
    __syncthreads();
#pragma unroll
    for (int i = ty; i < 32; i += 8) {
        float v = tile[tx][i];
        __nv_bfloat16 h = __float2bfloat16(v);
        size_t o = (size_t)(n0 + i) * K + k0 + tx;
        hi[o] = h;
        lo[o] = __float2bfloat16(v - __bfloat162float(h));
    }
}

// ---------------------------------------------------------------------------
// cp.async double-buffered mma.sync bf16 3-pass GEMM
// D[M,N] = A[M,K] @ B^T[N,K] + bias.  CTA tile 128x128, BK=32, 8 warps.
// mode 0: scatter split bf16 hi/lo into g_q*/g_k*/g_v*
// mode 1: fp32 row-major store into Cout
// ---------------------------------------------------------------------------
#define BK 32
#define LDS_ROW 40                 // 80B rows, 16B-aligned, conflict-free
#define G_BUF 10240                // 128*40*2
#define G_STAGE (4 * G_BUF)        // 40960
#define GEMM_SMEM (2 * G_STAGE)    // 81920

__device__ __forceinline__ void gemm_stage_load(
    uint32_t sb,
    const __nv_bfloat16* Ahi, const __nv_bfloat16* Alo,
    const __nv_bfloat16* Bhi, const __nv_bfloat16* Blo,
    int m0, int n0, int k0, int tid)
{
    const int K = CC;
#pragma unroll
    for (int sub = 0; sub < 2; sub++) {
        const int idx = sub * 256 + tid;
        const int r = idx >> 2;
        const int c = (idx & 3) * 8;
        const uint32_t so = (uint32_t)(r * LDS_ROW + c) * 2;
        const size_t goA = (size_t)(m0 + r) * K + k0 + c;
        const size_t goB = (size_t)(n0 + r) * K + k0 + c;
        cp16(sb + 0 * G_BUF + so, Ahi + goA);
        cp16(sb + 1 * G_BUF + so, Alo + goA);
        cp16(sb + 2 * G_BUF + so, Bhi + goB);
        cp16(sb + 3 * G_BUF + so, Blo + goB);
    }
}

__global__ __launch_bounds__(256) void tc_gemm_kernel(
    const __nv_bfloat16* __restrict__ Ahi, const __nv_bfloat16* __restrict__ Alo,
    const __nv_bfloat16* __restrict__ Bhi, const __nv_bfloat16* __restrict__ Blo,
    const float* __restrict__ bias, float* __restrict__ Cout,
    int N, int mode)
{
    extern __shared__ __align__(16) char dsm[];
    const uint32_t sb0 = smem_u32(dsm);

    const int tid = threadIdx.x;
    const int warp = tid >> 5;
    const int lane = tid & 31;
    const int warpM = warp >> 2;
    const int warpN = warp & 3;
    const int m0 = blockIdx.y * 128;
    const int n0 = blockIdx.x * 128;

    float acc[4][4][4];
#pragma unroll
    for (int mt = 0; mt < 4; mt++)
#pragma unroll
        for (int nt = 0; nt < 4; nt++)
#pragma unroll
            for (int i = 0; i < 4; i++) acc[mt][nt][i] = 0.0f;

    const int aRow = warpM * 64 + (lane & 15);
    const int aK   = (lane >> 4) * 8;
    const int bRow = warpN * 32 + (lane & 7);
    const int bK   = ((lane >> 3) & 1) * 8;

    const int NCH = CC / BK;   // 32

    gemm_stage_load(sb0, Ahi, Alo, Bhi, Blo, m0, n0, 0, tid);
    cp_commit();

    for (int ch = 0; ch < NCH; ch++) {
        if (ch + 1 < NCH)
            gemm_stage_load(sb0 + ((ch + 1) & 1) * G_STAGE,
                            Ahi, Alo, Bhi, Blo, m0, n0, (ch + 1) * BK, tid);
        cp_commit();            // empty group on last iter keeps count aligned
        cp_wait<1>();
        __syncthreads();

        const uint32_t st = sb0 + (ch & 1) * G_STAGE;
        const uint32_t sa_hi = st, sa_lo = st + G_BUF;
        const uint32_t sb_hi = st + 2 * G_BUF, sb_lo = st + 3 * G_BUF;

#pragma unroll
        for (int ks = 0; ks < 2; ks++) {
            const int kk = ks * 16;
            uint32_t afh[4][4], afl[4][4], bfh[4][2], bfl[4][2];
#pragma unroll
            for (int mt = 0; mt < 4; mt++) {
                const uint32_t off = ((aRow + mt * 16) * LDS_ROW + aK + kk) * 2;
                ldmatrix_x4(afh[mt], sa_hi + off);
                ldmatrix_x4(afl[mt], sa_lo + off);
            }
#pragma unroll
            for (int nt = 0; nt < 4; nt++) {
                const uint32_t off = ((bRow + nt * 8) * LDS_ROW + bK + kk) * 2;
                ldmatrix_x2(bfh[nt], sb_hi + off);
                ldmatrix_x2(bfl[nt], sb_lo + off);
            }
#pragma unroll
            for (int mt = 0; mt < 4; mt++)
#pragma unroll
                for (int nt = 0; nt < 4; nt++) {
                    mma_bf16(acc[mt][nt], afh[mt], bfh[nt]);
                    mma_bf16(acc[mt][nt], afh[mt], bfl[nt]);
                    mma_bf16(acc[mt][nt], afl[mt], bfh[nt]);
                }
        }
        __syncthreads();
    }

    // epilogue
#pragma unroll
    for (int mt = 0; mt < 4; mt++) {
#pragma unroll
        for (int i = 0; i < 2; i++) {
            const int m = m0 + warpM * 64 + mt * 16 + (lane >> 2) + i * 8;
            const int b = m >> 11;
            const int t = m & 2047;
#pragma unroll
            for (int nt = 0; nt < 4; nt++) {
                const int n = n0 + warpN * 32 + nt * 8 + (lane & 3) * 2;
                const float v0 = acc[mt][nt][i * 2 + 0] + bias[n];
                const float v1 = acc[mt][nt][i * 2 + 1] + bias[n + 1];
                if (mode == 0) {
                    const int region = n >> 10;      // 0=q 1=k 2=v
                    const int cc = n & 1023;
                    const int h = cc >> 6;
                    const int dd = cc & 63;
                    __nv_bfloat16* dh = (region == 0) ? g_qh
                                      : (region == 1) ? g_kh : g_vh;
                    __nv_bfloat16* dl = (region == 0) ? g_ql
                                      : (region == 1) ? g_kl : g_vl;
                    const size_t o = (((size_t)b * HH + h) * TT + t) * DD + dd;
                    const float h0 = __bfloat162float(__float2bfloat16(v0));
                    const float h1 = __bfloat162float(__float2bfloat16(v1));
                    *(uint32_t*)(dh + o) = pack_bf16(v0, v1);
                    *(uint32_t*)(dl + o) = pack_bf16(v0 - h0, v1 - h1);
                } else {
                    float2 w; w.x = v0; w.y = v1;
                    *(float2*)(Cout + (size_t)m * N + n) = w;
                }
            }
        }
    }
}

// ---------------------------------------------------------------------------
// cp.async double-buffered tensor-core flash attention (hi/lo compensated).
// Grid: (T/128, B*H). Block: 256 threads (8 warps x 16 query rows).
// Inputs pre-split bf16 hi/lo; output written pre-split to g_yh/g_yl.
// ---------------------------------------------------------------------------
#define KVROW 72                     // 144B rows, 16B-aligned, conflict-free
#define A_BUF (64 * KVROW * 2)       // 9216
#define A_STAGE (4 * A_BUF + 256)    // 37120 (am tile at +36864)
#define ATTN_SMEM (2 * A_STAGE)      // 74240

__device__ __forceinline__ void attn_stage_load(
    uint32_t sb,
    const __nv_bfloat16* Kh, const __nv_bfloat16* Kl,
    const __nv_bfloat16* Vh, const __nv_bfloat16* Vl,
    const float* amp, int k0, int tid)
{
    const int r = tid >> 2;
    const int s2 = (tid & 3) * 2;
#pragma unroll
    for (int i = 0; i < 2; i++) {
        const int seg = s2 + i;
        const uint32_t so = (uint32_t)(r * KVROW + seg * 8) * 2;
        const size_t go = (size_t)(k0 + r) * DD + seg * 8;
        cp16(sb + 0 * A_BUF + so, Kh + go);
        cp16(sb + 1 * A_BUF + so, Kl + go);
        cp16(sb + 2 * A_BUF + so, Vh + go);
        cp16(sb + 3 * A_BUF + so, Vl + go);
    }
    if (tid < 16) cp16(sb + 4 * A_BUF + tid * 16, amp + k0 + tid * 4);
}

__global__ __launch_bounds__(256) void attn_tc_kernel(const float* __restrict__ am)
{
    extern __shared__ __align__(16) char dsm[];
    const uint32_t sb0 = smem_u32(dsm);

    const int tid = threadIdx.x;
    const int warp = tid >> 5;
    const int lane = tid & 31;
    const int g = lane >> 2;
    const int c = lane & 3;
    const int bh = blockIdx.y;
    const int b = bh >> 4;
    const int h = bh & 15;
    const int qtile = gridDim.x - 1 - blockIdx.x;   // heavy CTAs first
    const int q0 = qtile * 128;

    const int r1 = q0 + warp * 16 + g;
    const int r2 = r1 + 8;

    const __nv_bfloat16* Qh = g_qh + (size_t)bh * TT * DD;
    const __nv_bfloat16* Ql = g_ql + (size_t)bh * TT * DD;
    const __nv_bfloat16* Kh = g_kh + (size_t)bh * TT * DD;
    const __nv_bfloat16* Kl = g_kl + (size_t)bh * TT * DD;
    const __nv_bfloat16* Vh = g_vh + (size_t)bh * TT * DD;
    const __nv_bfloat16* Vl = g_vl + (size_t)bh * TT * DD;
    const float* amp = am + b * TT;

    // Q fragments straight from pre-split globals
    uint32_t qh[4][4], ql[4][4];
#pragma unroll
    for (int ks = 0; ks < 4; ks++) {
#pragma unroll
        for (int half = 0; half < 2; half++) {
            const int col = ks * 16 + half * 8 + c * 2;
            qh[ks][half * 2 + 0] = *(const uint32_t*)(Qh + (size_t)r1 * DD + col);
            qh[ks][half * 2 + 1] = *(const uint32_t*)(Qh + (size_t)r2 * DD + col);
            ql[ks][half * 2 + 0] = *(const uint32_t*)(Ql + (size_t)r1 * DD + col);
            ql[ks][half * 2 + 1] = *(const uint32_t*)(Ql + (size_t)r2 * DD + col);
        }
    }

    float o[8][4];
#pragma unroll
    for (int nt = 0; nt < 8; nt++)
#pragma unroll
        for (int i = 0; i < 4; i++) o[nt][i] = 0.0f;
    float m0v = -1e30f, m1v = -1e30f;
    float l0 = 0.0f, l1 = 0.0f;

    const int g4 = lane >> 3;
    const int l8 = lane & 7;

    const int nkv = 2 * (qtile + 1);
    attn_stage_load(sb0, Kh, Kl, Vh, Vl, amp, 0, tid);
    cp_commit();

    for (int kt = 0; kt < nkv; kt++) {
        const int k0 = kt * 64;
        if (kt + 1 < nkv)
            attn_stage_load(sb0 + ((kt + 1) & 1) * A_STAGE,
                            Kh, Kl, Vh, Vl, amp, (kt + 1) * 64, tid);
        cp_commit();
        cp_wait<1>();
        __syncthreads();

        const uint32_t st = sb0 + (kt & 1) * A_STAGE;
        const uint32_t skh = st, skl = st + A_BUF;
        const uint32_t svh = st + 2 * A_BUF, svl = st + 3 * A_BUF;
        const float* amS = (const float*)(dsm + (kt & 1) * A_STAGE + 4 * A_BUF);
        const bool needCausal = (kt >= 2 * qtile);

        // --- S = Q @ K^T (3-term)
        float s[8][4];
#pragma unroll
        for (int nt = 0; nt < 8; nt++)
#pragma unroll
            for (int i = 0; i < 4; i++) s[nt][i] = 0.0f;

#pragma unroll
        for (int ks = 0; ks < 4; ks++) {
#pragma unroll
            for (int nt2 = 0; nt2 < 4; nt2++) {
                const uint32_t off =
                    ((nt2 * 16 + (g4 >> 1) * 8 + l8) * KVROW +
                     ks * 16 + (g4 & 1) * 8) * 2;
                uint32_t bhf[4], blf[4];
                ldmatrix_x4(bhf, skh + off);
                ldmatrix_x4(blf, skl + off);
                mma_bf16(s[nt2 * 2 + 0], qh[ks], bhf);
                mma_bf16(s[nt2 * 2 + 1], qh[ks], bhf + 2);
                mma_bf16(s[nt2 * 2 + 0], qh[ks], blf);
                mma_bf16(s[nt2 * 2 + 1], qh[ks], blf + 2);
                mma_bf16(s[nt2 * 2 + 0], ql[ks], bhf);
                mma_bf16(s[nt2 * 2 + 1], ql[ks], bhf + 2);
            }
        }

        // --- scale + masks
#pragma unroll
        for (int nt = 0; nt < 8; nt++) {
            const int colb = nt * 8 + c * 2;
            const float a0 = amS[colb] * NEGINF;
            const float a1 = amS[colb + 1] * NEGINF;
            s[nt][0] = s[nt][0] * 0.125f + a0;
            s[nt][1] = s[nt][1] * 0.125f + a1;
            s[nt][2] = s[nt][2] * 0.125f + a0;
            s[nt][3] = s[nt][3] * 0.125f + a1;
            if (needCausal) {
                const int kg0 = k0 + colb;
                if (kg0 > r1)     s[nt][0] = -1e30f;
                if (kg0 + 1 > r1) s[nt][1] = -1e30f;
                if (kg0 > r2)     s[nt][2] = -1e30f;
                if (kg0 + 1 > r2) s[nt][3] = -1e30f;
            }
        }

        // --- online softmax
        float t0 = -1e30f, t1 = -1e30f;
#pragma unroll
        for (int nt = 0; nt < 8; nt++) {
            t0 = fmaxf(t0, fmaxf(s[nt][0], s[nt][1]));
            t1 = fmaxf(t1, fmaxf(s[nt][2], s[nt][3]));
        }
        t0 = fmaxf(t0, __shfl_xor_sync(0xffffffffu, t0, 1));
        t0 = fmaxf(t0, __shfl_xor_sync(0xffffffffu, t0, 2));
        t1 = fmaxf(t1, __shfl_xor_sync(0xffffffffu, t1, 1));
        t1 = fmaxf(t1, __shfl_xor_sync(0xffffffffu, t1, 2));

        const float mn0 = fmaxf(m0v, t0);
        const float mn1 = fmaxf(m1v, t1);
        const float cr0 = __expf(m0v - mn0);
        const float cr1 = __expf(m1v - mn1);
        m0v = mn0; m1v = mn1;

        float s0 = 0.0f, s1 = 0.0f;
#pragma unroll
        for (int nt = 0; nt < 8; nt++) {
            s[nt][0] = __expf(s[nt][0] - mn0);
            s[nt][1] = __expf(s[nt][1] - mn0);
            s[nt][2] = __expf(s[nt][2] - mn1);
            s[nt][3] = __expf(s[nt][3] - mn1);
            s0 += s[nt][0] + s[nt][1];
            s1 += s[nt][2] + s[nt][3];
            o[nt][0] *= cr0; o[nt][1] *= cr0;
            o[nt][2] *= cr1; o[nt][3] *= cr1;
        }
        s0 += __shfl_xor_sync(0xffffffffu, s0, 1);
        s0 += __shfl_xor_sync(0xffffffffu, s0, 2);
        s1 += __shfl_xor_sync(0xffffffffu, s1, 1);
        s1 += __shfl_xor_sync(0xffffffffu, s1, 2);
        l0 = l0 * cr0 + s0;
        l1 = l1 * cr1 + s1;

        // --- O += P @ V (3-term)
#pragma unroll
        for (int j = 0; j < 4; j++) {
            uint32_t pfh[4], pfl[4];
            {
                const float p00 = s[2 * j][0],     p01 = s[2 * j][1];
                const float p10 = s[2 * j][2],     p11 = s[2 * j][3];
                const float p20 = s[2 * j + 1][0], p21 = s[2 * j + 1][1];
                const float p30 = s[2 * j + 1][2], p31 = s[2 * j + 1][3];
                const float h00 = __bfloat162float(__float2bfloat16(p00));
                const float h01 = __bfloat162float(__float2bfloat16(p01));
                const float h10 = __bfloat162float(__float2bfloat16(p10));
                const float h11 = __bfloat162float(__float2bfloat16(p11));
                const float h20 = __bfloat162float(__float2bfloat16(p20));
                const float h21 = __bfloat162float(__float2bfloat16(p21));
                const float h30 = __bfloat162float(__float2bfloat16(p30));
                const float h31 = __bfloat162float(__float2bfloat16(p31));
                pfh[0] = pack_bf16(p00, p01);
                pfh[1] = pack_bf16(p10, p11);
                pfh[2] = pack_bf16(p20, p21);
                pfh[3] = pack_bf16(p30, p31);
                pfl[0] = pack_bf16(p00 - h00, p01 - h01);
                pfl[1] = pack_bf16(p10 - h10, p11 - h11);
                pfl[2] = pack_bf16(p20 - h20, p21 - h21);
                pfl[3] = pack_bf16(p30 - h30, p31 - h31);
            }
#pragma unroll
            for (int nt2 = 0; nt2 < 4; nt2++) {
                const uint32_t off =
                    ((16 * j + (g4 & 1) * 8 + l8) * KVROW +
                     nt2 * 16 + (g4 >> 1) * 8) * 2;
                uint32_t vhf[4], vlf[4];
                ldmatrix_x4_trans(vhf, svh + off);
                ldmatrix_x4_trans(vlf, svl + off);
                mma_bf16(o[nt2 * 2 + 0], pfh, vhf);
                mma_bf16(o[nt2 * 2 + 1], pfh, vhf + 2);
                mma_bf16(o[nt2 * 2 + 0], pfh, vlf);
                mma_bf16(o[nt2 * 2 + 1], pfh, vlf + 2);
                mma_bf16(o[nt2 * 2 + 0], pfl, vhf);
                mma_bf16(o[nt2 * 2 + 1], pfl, vhf + 2);
            }
        }
        __syncthreads();
    }

    // --- epilogue: normalize, split, write g_yh/g_yl
    const float i0 = 1.0f / l0;
    const float i1 = 1.0f / l1;
    __nv_bfloat16* Yh1 = g_yh + (size_t)(b * TT + r1) * CC + h * DD;
    __nv_bfloat16* Yl1 = g_yl + (size_t)(b * TT + r1) * CC + h * DD;
    __nv_bfloat16* Yh2 = g_yh + (size_t)(b * TT + r2) * CC + h * DD;
    __nv_bfloat16* Yl2 = g_yl + (size_t)(b * TT + r2) * CC + h * DD;
#pragma unroll
    for (int nt = 0; nt < 8; nt++) {
        const int col = nt * 8 + c * 2;
        const float w0x = o[nt][0] * i0, w0y = o[nt][1] * i0;
        const float w1x = o[nt][2] * i1, w1y = o[nt][3] * i1;
        const float h0x = __bfloat162float(__float2bfloat16(w0x));
        const float h0y = __bfloat162float(__float2bfloat16(w0y));
        const float h1x = __bfloat162float(__float2bfloat16(w1x));
        const float h1y = __bfloat162float(__float2bfloat16(w1y));
        *(uint32_t*)(Yh1 + col) = pack_bf16(w0x, w0y);
        *(uint32_t*)(Yl1 + col) = pack_bf16(w0x - h0x, w0y - h0y);
        *(uint32_t*)(Yh2 + col) = pack_bf16(w1x, w1y);
        *(uint32_t*)(Yl2 + col) = pack_bf16(w1x - h1x, w1y - h1y);
    }
}

// ---------------------------------------------------------------------------
extern "C" void kernel_launch(void* const* d_in, const int* in_sizes, int n_in,
                              void* d_out, int out_size)
{
    (void)in_sizes; (void)n_in; (void)out_size;
    const float* x  = (const float*)d_in[0];   // [B,T,C]
    const float* am = (const float*)d_in[1];   // [B,T]
    const float* Wa = (const float*)d_in[2];   // [C,3C]
    const float* ba = (const float*)d_in[3];   // [3C]
    const float* Wp = (const float*)d_in[4];   // [C,C]
    const float* bp = (const float*)d_in[5];   // [C]
    float* out = (float*)d_out;                // [B,T,C]

    cudaFuncSetAttribute(tc_gemm_kernel,
                         cudaFuncAttributeMaxDynamicSharedMemorySize, GEMM_SMEM);
    cudaFuncSetAttribute(attn_tc_kernel,
                         cudaFuncAttributeMaxDynamicSharedMemorySize, ATTN_SMEM);

    __nv_bfloat16 *xh, *xl, *yh, *yl, *wah, *wal, *wph, *wpl;
    cudaGetSymbolAddress((void**)&xh,  g_xh);
    cudaGetSymbolAddress((void**)&xl,  g_xl);
    cudaGetSymbolAddress((void**)&yh,  g_yh);
    cudaGetSymbolAddress((void**)&yl,  g_yl);
    cudaGetSymbolAddress((void**)&wah, g_wah);
    cudaGetSymbolAddress((void**)&wal, g_wal);
    cudaGetSymbolAddress((void**)&wph, g_wph);
    cudaGetSymbolAddress((void**)&wpl, g_wpl);

    const int M = BB * TT;          // 4096

    // 0) operand conversion
    split_kernel<<<(M * CC) / 256, 256>>>(x, xh, xl, M * CC);
    transpose_split_kernel<<<dim3(3 * CC / 32, CC / 32), dim3(32, 8)>>>(
        Wa, wah, wal, CC, 3 * CC);
    transpose_split_kernel<<<dim3(CC / 32, CC / 32), dim3(32, 8)>>>(
        Wp, wph, wpl, CC, CC);

    // 1) QKV projection -> pre-split q/k/v hi/lo [B,H,T,D]
    tc_gemm_kernel<<<dim3(3 * CC / 128, M / 128), 256, GEMM_SMEM>>>(
        xh, xl, wah, wal, ba, nullptr, 3 * CC, 0);

    // 2) flash attention -> pre-split y hi/lo [B,T,C]
    attn_tc_kernel<<<dim3(TT / 128, BB * HH), 256, ATTN_SMEM>>>(am);

    // 3) output projection -> d_out fp32
    tc_gemm_kernel<<<dim3(CC / 128, M / 128), 256, GEMM_SMEM>>>(
        yh, yl, wph, wpl, bp, out, CC, 1);
}

// round 7
// speedup vs baseline: 4.1949x; 1.1012x over previous
#include <cuda_runtime.h>
#include <cuda_bf16.h>
#include <cstdint>
#include <cstddef>

// Problem constants
#define BB 2
#define TT 2048
#define CC 1024
#define HH 16
#define DD 64
#define NEGINF (-1e10f)

// ---------------------------------------------------------------------------
// Device-global scratch (no allocation allowed). q/k/v/y live ONLY as
// pre-split bf16 hi/lo pairs.
// ---------------------------------------------------------------------------
__device__ __nv_bfloat16 g_qh[(size_t)BB * HH * TT * DD];
__device__ __nv_bfloat16 g_ql[(size_t)BB * HH * TT * DD];
__device__ __nv_bfloat16 g_kh[(size_t)BB * HH * TT * DD];
__device__ __nv_bfloat16 g_kl[(size_t)BB * HH * TT * DD];
__device__ __nv_bfloat16 g_vh[(size_t)BB * HH * TT * DD];
__device__ __nv_bfloat16 g_vl[(size_t)BB * HH * TT * DD];
__device__ __nv_bfloat16 g_yh[(size_t)BB * TT * CC];
__device__ __nv_bfloat16 g_yl[(size_t)BB * TT * CC];

__device__ __nv_bfloat16 g_xh[(size_t)BB * TT * CC];
__device__ __nv_bfloat16 g_xl[(size_t)BB * TT * CC];
__device__ __nv_bfloat16 g_wah[(size_t)3 * CC * CC];
__device__ __nv_bfloat16 g_wal[(size_t)3 * CC * CC];
__device__ __nv_bfloat16 g_wph[(size_t)CC * CC];
__device__ __nv_bfloat16 g_wpl[(size_t)CC * CC];

// ---------------------------------------------------------------------------
// PTX helpers (sm_80+ — legal on plain sm_100 target)
// ---------------------------------------------------------------------------
__device__ __forceinline__ uint32_t smem_u32(const void* p) {
    return (uint32_t)__cvta_generic_to_shared(p);
}
__device__ __forceinline__ void cp16(uint32_t s, const void* g) {
    asm volatile("cp.async.cg.shared.global [%0], [%1], 16;" :: "r"(s), "l"(g));
}
__device__ __forceinline__ void cp_commit() {
    asm volatile("cp.async.commit_group;" ::: "memory");
}
template <int N>
__device__ __forceinline__ void cp_wait() {
    asm volatile("cp.async.wait_group %0;" :: "n"(N) : "memory");
}
__device__ __forceinline__ void ldmatrix_x4(uint32_t* r, uint32_t addr) {
    asm volatile("ldmatrix.sync.aligned.m8n8.x4.shared.b16 {%0,%1,%2,%3}, [%4];"
                 : "=r"(r[0]), "=r"(r[1]), "=r"(r[2]), "=r"(r[3]) : "r"(addr));
}
__device__ __forceinline__ void ldmatrix_x4_trans(uint32_t* r, uint32_t addr) {
    asm volatile("ldmatrix.sync.aligned.m8n8.x4.trans.shared.b16 {%0,%1,%2,%3}, [%4];"
                 : "=r"(r[0]), "=r"(r[1]), "=r"(r[2]), "=r"(r[3]) : "r"(addr));
}
__device__ __forceinline__ void mma_bf16(float* d, const uint32_t* a,
                                         const uint32_t* b) {
    asm volatile(
        "mma.sync.aligned.m16n8k16.row.col.f32.bf16.bf16.f32 "
        "{%0,%1,%2,%3}, {%4,%5,%6,%7}, {%8,%9}, {%0,%1,%2,%3};"
        : "+f"(d[0]), "+f"(d[1]), "+f"(d[2]), "+f"(d[3])
        : "r"(a[0]), "r"(a[1]), "r"(a[2]), "r"(a[3]), "r"(b[0]), "r"(b[1]));
}
// pack two f32 as bf16x2: first arg -> low half
__device__ __forceinline__ uint32_t pack_bf16(float lo, float hi) {
    uint32_t r;
    asm("cvt.rn.bf16x2.f32 %0, %1, %2;" : "=r"(r) : "f"(hi), "f"(lo));
    return r;
}

// ---------------------------------------------------------------------------
// Convert kernels: fp32 -> (bf16 hi, bf16 lo)
// ---------------------------------------------------------------------------
__global__ void split_kernel(const float* __restrict__ src,
                             __nv_bfloat16* __restrict__ hi,
                             __nv_bfloat16* __restrict__ lo, int n)
{
    int i = blockIdx.x * blockDim.x + threadIdx.x;
    if (i < n) {
        float v = src[i];
        __nv_bfloat16 h = __float2bfloat16(v);
        hi[i] = h;
        lo[i] = __float2bfloat16(v - __bfloat162float(h));
    }
}

__global__ void transpose_split_kernel(const float* __restrict__ src,
                                       __nv_bfloat16* __restrict__ hi,
                                       __nv_bfloat16* __restrict__ lo,
                                       int K, int N)
{
    __shared__ float tile[32][33];
    const int k0 = blockIdx.y * 32;
    const int n0 = blockIdx.x * 32;
    const int tx = threadIdx.x, ty = threadIdx.y;  // (32, 8)
#pragma unroll
    for (int i = ty; i < 32; i += 8)
        tile[i][tx] = src[(size_t)(k0 + i) * N + n0 + tx];
    __syncthreads();
#pragma unroll
    for (int i = ty; i < 32; i += 8) {
        float v = tile[tx][i];
        __nv_bfloat16 h = __float2bfloat16(v);
        size_t o = (size_t)(n0 + i) * K + k0 + tx;
        hi[o] = h;
        lo[o] = __float2bfloat16(v - __bfloat162float(h));
    }
}

// ---------------------------------------------------------------------------
// cp.async double-buffered mma.sync bf16 3-pass GEMM
// D[M,N] = A[M,K] @ B^T[N,K] + bias.  CTA tile 128x128, BK=32, 8 warps.
// Single barrier per chunk; prefetch interleaved with MMA; B via ldmatrix.x4.
// ---------------------------------------------------------------------------
#define BK 32
#define LDS_ROW 40                 // 80B rows, 16B-aligned, conflict-free
#define G_BUF 10240                // 128*40*2
#define G_STAGE (4 * G_BUF)        // 40960
#define GEMM_SMEM (2 * G_STAGE)    // 81920

__device__ __forceinline__ void gemm_stage_load(
    uint32_t sb,
    const __nv_bfloat16* Ahi, const __nv_bfloat16* Alo,
    const __nv_bfloat16* Bhi, const __nv_bfloat16* Blo,
    int m0, int n0, int k0, int tid, int sub)
{
    const int K = CC;
    const int idx = sub * 256 + tid;
    const int r = idx >> 2;
    const int c = (idx & 3) * 8;
    const uint32_t so = (uint32_t)(r * LDS_ROW + c) * 2;
    const size_t goA = (size_t)(m0 + r) * K + k0 + c;
    const size_t goB = (size_t)(n0 + r) * K + k0 + c;
    cp16(sb + 0 * G_BUF + so, Ahi + goA);
    cp16(sb + 1 * G_BUF + so, Alo + goA);
    cp16(sb + 2 * G_BUF + so, Bhi + goB);
    cp16(sb + 3 * G_BUF + so, Blo + goB);
}

__global__ __launch_bounds__(256, 2) void tc_gemm_kernel(
    const __nv_bfloat16* __restrict__ Ahi, const __nv_bfloat16* __restrict__ Alo,
    const __nv_bfloat16* __restrict__ Bhi, const __nv_bfloat16* __restrict__ Blo,
    const float* __restrict__ bias, float* __restrict__ Cout,
    int N, int mode)
{
    extern __shared__ __align__(16) char dsm[];
    const uint32_t sb0 = smem_u32(dsm);

    const int tid = threadIdx.x;
    const int warp = tid >> 5;
    const int lane = tid & 31;
    const int warpM = warp >> 2;
    const int warpN = warp & 3;
    const int m0 = blockIdx.y * 128;
    const int n0 = blockIdx.x * 128;

    float acc[4][4][4];
#pragma unroll
    for (int mt = 0; mt < 4; mt++)
#pragma unroll
        for (int nt = 0; nt < 4; nt++)
#pragma unroll
            for (int i = 0; i < 4; i++) acc[mt][nt][i] = 0.0f;

    const int aRow = warpM * 64 + (lane & 15);
    const int aK   = (lane >> 4) * 8;
    // ldmatrix.x4 B address: lanes 0-7 rows of nt-even @k, 8-15 @k+8,
    //                        16-23 rows of nt-odd @k, 24-31 @k+8
    const int bRow4 = warpN * 32 + (lane >> 4) * 8 + (lane & 7);
    const int bK4   = ((lane >> 3) & 1) * 8;

    const int NCH = CC / BK;   // 32

    gemm_stage_load(sb0, Ahi, Alo, Bhi, Blo, m0, n0, 0, tid, 0);
    gemm_stage_load(sb0, Ahi, Alo, Bhi, Blo, m0, n0, 0, tid, 1);
    cp_commit();

    for (int ch = 0; ch < NCH; ch++) {
        cp_wait<0>();
        __syncthreads();

        const uint32_t st = sb0 + (ch & 1) * G_STAGE;
        const uint32_t sa_hi = st, sa_lo = st + G_BUF;
        const uint32_t sb_hi = st + 2 * G_BUF, sb_lo = st + 3 * G_BUF;
        const bool pf = (ch + 1 < NCH);
        const uint32_t pb = sb0 + ((ch + 1) & 1) * G_STAGE;

        if (pf)
            gemm_stage_load(pb, Ahi, Alo, Bhi, Blo, m0, n0, (ch + 1) * BK, tid, 0);

#pragma unroll
        for (int ks = 0; ks < 2; ks++) {
            const int kk = ks * 16;
            uint32_t afh[4][4], afl[4][4], bfr[2][2][4];
#pragma unroll
            for (int mt = 0; mt < 4; mt++) {
                const uint32_t off = ((aRow + mt * 16) * LDS_ROW + aK + kk) * 2;
                ldmatrix_x4(afh[mt], sa_hi + off);
                ldmatrix_x4(afl[mt], sa_lo + off);
            }
#pragma unroll
            for (int bp = 0; bp < 2; bp++) {
                const uint32_t off = ((bRow4 + bp * 16) * LDS_ROW + bK4 + kk) * 2;
                ldmatrix_x4(bfr[0][bp], sb_hi + off);
                ldmatrix_x4(bfr[1][bp], sb_lo + off);
            }
#pragma unroll
            for (int mt = 0; mt < 4; mt++)
#pragma unroll
                for (int nt = 0; nt < 4; nt++) {
                    const uint32_t* bh = bfr[0][nt >> 1] + (nt & 1) * 2;
                    const uint32_t* bl = bfr[1][nt >> 1] + (nt & 1) * 2;
                    mma_bf16(acc[mt][nt], afh[mt], bh);
                    mma_bf16(acc[mt][nt], afh[mt], bl);
                    mma_bf16(acc[mt][nt], afl[mt], bh);
                }
            if (ks == 0) {
                if (pf)
                    gemm_stage_load(pb, Ahi, Alo, Bhi, Blo, m0, n0,
                                    (ch + 1) * BK, tid, 1);
                cp_commit();
            }
        }
    }

    // epilogue
#pragma unroll
    for (int mt = 0; mt < 4; mt++) {
#pragma unroll
        for (int i = 0; i < 2; i++) {
            const int m = m0 + warpM * 64 + mt * 16 + (lane >> 2) + i * 8;
            const int b = m >> 11;
            const int t = m & 2047;
#pragma unroll
            for (int nt = 0; nt < 4; nt++) {
                const int n = n0 + warpN * 32 + nt * 8 + (lane & 3) * 2;
                const float v0 = acc[mt][nt][i * 2 + 0] + bias[n];
                const float v1 = acc[mt][nt][i * 2 + 1] + bias[n + 1];
                if (mode == 0) {
                    const int region = n >> 10;      // 0=q 1=k 2=v
                    const int cc = n & 1023;
                    const int h = cc >> 6;
                    const int dd = cc & 63;
                    __nv_bfloat16* dh = (region == 0) ? g_qh
                                      : (region == 1) ? g_kh : g_vh;
                    __nv_bfloat16* dl = (region == 0) ? g_ql
                                      : (region == 1) ? g_kl : g_vl;
                    const size_t o = (((size_t)b * HH + h) * TT + t) * DD + dd;
                    const float h0 = __bfloat162float(__float2bfloat16(v0));
                    const float h1 = __bfloat162float(__float2bfloat16(v1));
                    *(uint32_t*)(dh + o) = pack_bf16(v0, v1);
                    *(uint32_t*)(dl + o) = pack_bf16(v0 - h0, v1 - h1);
                } else {
                    float2 w; w.x = v0; w.y = v1;
                    *(float2*)(Cout + (size_t)m * N + n) = w;
                }
            }
        }
    }
}

// ---------------------------------------------------------------------------
// cp.async double-buffered tensor-core flash attention (hi/lo compensated).
// Grid: (T/128, B*H). Block: 256 threads. Single barrier per KV tile.
// ---------------------------------------------------------------------------
#define KVROW 72                     // 144B rows, conflict-free
#define A_BUF (64 * KVROW * 2)       // 9216
#define A_STAGE (4 * A_BUF + 256)    // 37120 (am tile at +36864)
#define ATTN_SMEM (2 * A_STAGE)      // 74240

__device__ __forceinline__ void attn_stage_load(
    uint32_t sb,
    const __nv_bfloat16* Kh, const __nv_bfloat16* Kl,
    const __nv_bfloat16* Vh, const __nv_bfloat16* Vl,
    const float* amp, int k0, int tid)
{
    const int r = tid >> 2;
    const int s2 = (tid & 3) * 2;
#pragma unroll
    for (int i = 0; i < 2; i++) {
        const int seg = s2 + i;
        const uint32_t so = (uint32_t)(r * KVROW + seg * 8) * 2;
        const size_t go = (size_t)(k0 + r) * DD + seg * 8;
        cp16(sb + 0 * A_BUF + so, Kh + go);
        cp16(sb + 1 * A_BUF + so, Kl + go);
        cp16(sb + 2 * A_BUF + so, Vh + go);
        cp16(sb + 3 * A_BUF + so, Vl + go);
    }
    if (tid < 16) cp16(sb + 4 * A_BUF + tid * 16, amp + k0 + tid * 4);
}

__global__ __launch_bounds__(256) void attn_tc_kernel(const float* __restrict__ am)
{
    extern __shared__ __align__(16) char dsm[];
    const uint32_t sb0 = smem_u32(dsm);

    const int tid = threadIdx.x;
    const int warp = tid >> 5;
    const int lane = tid & 31;
    const int g = lane >> 2;
    const int c = lane & 3;
    const int bh = blockIdx.y;
    const int b = bh >> 4;
    const int h = bh & 15;
    const int qtile = gridDim.x - 1 - blockIdx.x;   // heavy CTAs first
    const int q0 = qtile * 128;

    const int r1 = q0 + warp * 16 + g;
    const int r2 = r1 + 8;

    const __nv_bfloat16* Qh = g_qh + (size_t)bh * TT * DD;
    const __nv_bfloat16* Ql = g_ql + (size_t)bh * TT * DD;
    const __nv_bfloat16* Kh = g_kh + (size_t)bh * TT * DD;
    const __nv_bfloat16* Kl = g_kl + (size_t)bh * TT * DD;
    const __nv_bfloat16* Vh = g_vh + (size_t)bh * TT * DD;
    const __nv_bfloat16* Vl = g_vl + (size_t)bh * TT * DD;
    const float* amp = am + b * TT;

    // Q fragments straight from pre-split globals
    uint32_t qh[4][4], ql[4][4];
#pragma unroll
    for (int ks = 0; ks < 4; ks++) {
#pragma unroll
        for (int half = 0; half < 2; half++) {
            const int col = ks * 16 + half * 8 + c * 2;
            qh[ks][half * 2 + 0] = *(const uint32_t*)(Qh + (size_t)r1 * DD + col);
            qh[ks][half * 2 + 1] = *(const uint32_t*)(Qh + (size_t)r2 * DD + col);
            ql[ks][half * 2 + 0] = *(const uint32_t*)(Ql + (size_t)r1 * DD + col);
            ql[ks][half * 2 + 1] = *(const uint32_t*)(Ql + (size_t)r2 * DD + col);
        }
    }

    float o[8][4];
#pragma unroll
    for (int nt = 0; nt < 8; nt++)
#pragma unroll
        for (int i = 0; i < 4; i++) o[nt][i] = 0.0f;
    float m0v = -1e30f, m1v = -1e30f;
    float l0 = 0.0f, l1 = 0.0f;

    const int g4 = lane >> 3;
    const int l8 = lane & 7;

    const int nkv = 2 * (qtile + 1);
    attn_stage_load(sb0, Kh, Kl, Vh, Vl, amp, 0, tid);
    cp_commit();

    for (int kt = 0; kt < nkv; kt++) {
        const int k0 = kt * 64;
        cp_wait<0>();
        __syncthreads();

        const uint32_t st = sb0 + (kt & 1) * A_STAGE;
        const uint32_t skh = st, skl = st + A_BUF;
        const uint32_t svh = st + 2 * A_BUF, svl = st + 3 * A_BUF;
        const float* amS = (const float*)(dsm + (kt & 1) * A_STAGE + 4 * A_BUF);
        const bool needCausal = (kt >= 2 * qtile);

        if (kt + 1 < nkv)
            attn_stage_load(sb0 + ((kt + 1) & 1) * A_STAGE,
                            Kh, Kl, Vh, Vl, amp, (kt + 1) * 64, tid);
        cp_commit();

        // --- S = Q @ K^T (3-term)
        float s[8][4];
#pragma unroll
        for (int nt = 0; nt < 8; nt++)
#pragma unroll
            for (int i = 0; i < 4; i++) s[nt][i] = 0.0f;

#pragma unroll
        for (int ks = 0; ks < 4; ks++) {
#pragma unroll
            for (int nt2 = 0; nt2 < 4; nt2++) {
                const uint32_t off =
                    ((nt2 * 16 + (g4 >> 1) * 8 + l8) * KVROW +
                     ks * 16 + (g4 & 1) * 8) * 2;
                uint32_t bhf[4], blf[4];
                ldmatrix_x4(bhf, skh + off);
                ldmatrix_x4(blf, skl + off);
                mma_bf16(s[nt2 * 2 + 0], qh[ks], bhf);
                mma_bf16(s[nt2 * 2 + 1], qh[ks], bhf + 2);
                mma_bf16(s[nt2 * 2 + 0], qh[ks], blf);
                mma_bf16(s[nt2 * 2 + 1], qh[ks], blf + 2);
                mma_bf16(s[nt2 * 2 + 0], ql[ks], bhf);
                mma_bf16(s[nt2 * 2 + 1], ql[ks], bhf + 2);
            }
        }

        // --- scale + masks
#pragma unroll
        for (int nt = 0; nt < 8; nt++) {
            const int colb = nt * 8 + c * 2;
            const float a0 = amS[colb] * NEGINF;
            const float a1 = amS[colb + 1] * NEGINF;
            s[nt][0] = s[nt][0] * 0.125f + a0;
            s[nt][1] = s[nt][1] * 0.125f + a1;
            s[nt][2] = s[nt][2] * 0.125f + a0;
            s[nt][3] = s[nt][3] * 0.125f + a1;
            if (needCausal) {
                const int kg0 = k0 + colb;
                if (kg0 > r1)     s[nt][0] = -1e30f;
                if (kg0 + 1 > r1) s[nt][1] = -1e30f;
                if (kg0 > r2)     s[nt][2] = -1e30f;
                if (kg0 + 1 > r2) s[nt][3] = -1e30f;
            }
        }

        // --- online softmax
        float t0 = -1e30f, t1 = -1e30f;
#pragma unroll
        for (int nt = 0; nt < 8; nt++) {
            t0 = fmaxf(t0, fmaxf(s[nt][0], s[nt][1]));
            t1 = fmaxf(t1, fmaxf(s[nt][2], s[nt][3]));
        }
        t0 = fmaxf(t0, __shfl_xor_sync(0xffffffffu, t0, 1));
        t0 = fmaxf(t0, __shfl_xor_sync(0xffffffffu, t0, 2));
        t1 = fmaxf(t1, __shfl_xor_sync(0xffffffffu, t1, 1));
        t1 = fmaxf(t1, __shfl_xor_sync(0xffffffffu, t1, 2));

        const float mn0 = fmaxf(m0v, t0);
        const float mn1 = fmaxf(m1v, t1);
        const float cr0 = __expf(m0v - mn0);
        const float cr1 = __expf(m1v - mn1);
        m0v = mn0; m1v = mn1;

        float s0 = 0.0f, s1 = 0.0f;
#pragma unroll
        for (int nt = 0; nt < 8; nt++) {
            s[nt][0] = __expf(s[nt][0] - mn0);
            s[nt][1] = __expf(s[nt][1] - mn0);
            s[nt][2] = __expf(s[nt][2] - mn1);
            s[nt][3] = __expf(s[nt][3] - mn1);
            s0 += s[nt][0] + s[nt][1];
            s1 += s[nt][2] + s[nt][3];
            o[nt][0] *= cr0; o[nt][1] *= cr0;
            o[nt][2] *= cr1; o[nt][3] *= cr1;
        }
        s0 += __shfl_xor_sync(0xffffffffu, s0, 1);
        s0 += __shfl_xor_sync(0xffffffffu, s0, 2);
        s1 += __shfl_xor_sync(0xffffffffu, s1, 1);
        s1 += __shfl_xor_sync(0xffffffffu, s1, 2);
        l0 = l0 * cr0 + s0;
        l1 = l1 * cr1 + s1;

        // --- O += P @ V (3-term)
#pragma unroll
        for (int j = 0; j < 4; j++) {
            uint32_t pfh[4], pfl[4];
            {
                const float p00 = s[2 * j][0],     p01 = s[2 * j][1];
                const float p10 = s[2 * j][2],     p11 = s[2 * j][3];
                const float p20 = s[2 * j + 1][0], p21 = s[2 * j + 1][1];
                const float p30 = s[2 * j + 1][2], p31 = s[2 * j + 1][3];
                const float h00 = __bfloat162float(__float2bfloat16(p00));
                const float h01 = __bfloat162float(__float2bfloat16(p01));
                const float h10 = __bfloat162float(__float2bfloat16(p10));
                const float h11 = __bfloat162float(__float2bfloat16(p11));
                const float h20 = __bfloat162float(__float2bfloat16(p20));
                const float h21 = __bfloat162float(__float2bfloat16(p21));
                const float h30 = __bfloat162float(__float2bfloat16(p30));
                const float h31 = __bfloat162float(__float2bfloat16(p31));
                pfh[0] = pack_bf16(p00, p01);
                pfh[1] = pack_bf16(p10, p11);
                pfh[2] = pack_bf16(p20, p21);
                pfh[3] = pack_bf16(p30, p31);
                pfl[0] = pack_bf16(p00 - h00, p01 - h01);
                pfl[1] = pack_bf16(p10 - h10, p11 - h11);
                pfl[2] = pack_bf16(p20 - h20, p21 - h21);
                pfl[3] = pack_bf16(p30 - h30, p31 - h31);
            }
#pragma unroll
            for (int nt2 = 0; nt2 < 4; nt2++) {
                const uint32_t off =
                    ((16 * j + (g4 & 1) * 8 + l8) * KVROW +
                     nt2 * 16 + (g4 >> 1) * 8) * 2;
                uint32_t vhf[4], vlf[4];
                ldmatrix_x4_trans(vhf, svh + off);
                ldmatrix_x4_trans(vlf, svl + off);
                mma_bf16(o[nt2 * 2 + 0], pfh, vhf);
                mma_bf16(o[nt2 * 2 + 1], pfh, vhf + 2);
                mma_bf16(o[nt2 * 2 + 0], pfh, vlf);
                mma_bf16(o[nt2 * 2 + 1], pfh, vlf + 2);
                mma_bf16(o[nt2 * 2 + 0], pfl, vhf);
                mma_bf16(o[nt2 * 2 + 1], pfl, vhf + 2);
            }
        }
    }

    // --- epilogue: normalize, split, write g_yh/g_yl
    const float i0 = 1.0f / l0;
    const float i1 = 1.0f / l1;
    __nv_bfloat16* Yh1 = g_yh + (size_t)(b * TT + r1) * CC + h * DD;
    __nv_bfloat16* Yl1 = g_yl + (size_t)(b * TT + r1) * CC + h * DD;
    __nv_bfloat16* Yh2 = g_yh + (size_t)(b * TT + r2) * CC + h * DD;
    __nv_bfloat16* Yl2 = g_yl + (size_t)(b * TT + r2) * CC + h * DD;
#pragma unroll
    for (int nt = 0; nt < 8; nt++) {
        const int col = nt * 8 + c * 2;
        const float w0x = o[nt][0] * i0, w0y = o[nt][1] * i0;
        const float w1x = o[nt][2] * i1, w1y = o[nt][3] * i1;
        const float h0x = __bfloat162float(__float2bfloat16(w0x));
        const float h0y = __bfloat162float(__float2bfloat16(w0y));
        const float h1x = __bfloat162float(__float2bfloat16(w1x));
        const float h1y = __bfloat162float(__float2bfloat16(w1y));
        *(uint32_t*)(Yh1 + col) = pack_bf16(w0x, w0y);
        *(uint32_t*)(Yl1 + col) = pack_bf16(w0x - h0x, w0y - h0y);
        *(uint32_t*)(Yh2 + col) = pack_bf16(w1x, w1y);
        *(uint32_t*)(Yl2 + col) = pack_bf16(w1x - h1x, w1y - h1y);
    }
}

// ---------------------------------------------------------------------------
extern "C" void kernel_launch(void* const* d_in, const int* in_sizes, int n_in,
                              void* d_out, int out_size)
{
    (void)in_sizes; (void)n_in; (void)out_size;
    const float* x  = (const float*)d_in[0];   // [B,T,C]
    const float* am = (const float*)d_in[1];   // [B,T]
    const float* Wa = (const float*)d_in[2];   // [C,3C]
    const float* ba = (const float*)d_in[3];   // [3C]
    const float* Wp = (const float*)d_in[4];   // [C,C]
    const float* bp = (const float*)d_in[5];   // [C]
    float* out = (float*)d_out;                // [B,T,C]

    cudaFuncSetAttribute(tc_gemm_kernel,
                         cudaFuncAttributeMaxDynamicSharedMemorySize, GEMM_SMEM);
    cudaFuncSetAttribute(attn_tc_kernel,
                         cudaFuncAttributeMaxDynamicSharedMemorySize, ATTN_SMEM);

    __nv_bfloat16 *xh, *xl, *yh, *yl, *wah, *wal, *wph, *wpl;
    cudaGetSymbolAddress((void**)&xh,  g_xh);
    cudaGetSymbolAddress((void**)&xl,  g_xl);
    cudaGetSymbolAddress((void**)&yh,  g_yh);
    cudaGetSymbolAddress((void**)&yl,  g_yl);
    cudaGetSymbolAddress((void**)&wah, g_wah);
    cudaGetSymbolAddress((void**)&wal, g_wal);
    cudaGetSymbolAddress((void**)&wph, g_wph);
    cudaGetSymbolAddress((void**)&wpl, g_wpl);

    const int M = BB * TT;          // 4096

    // 0) operand conversion
    split_kernel<<<(M * CC) / 256, 256>>>(x, xh, xl, M * CC);
    transpose_split_kernel<<<dim3(3 * CC / 32, CC / 32), dim3(32, 8)>>>(
        Wa, wah, wal, CC, 3 * CC);
    transpose_split_kernel<<<dim3(CC / 32, CC / 32), dim3(32, 8)>>>(
        Wp, wph, wpl, CC, CC);

    // 1) QKV projection -> pre-split q/k/v hi/lo [B,H,T,D]
    tc_gemm_kernel<<<dim3(3 * CC / 128, M / 128), 256, GEMM_SMEM>>>(
        xh, xl, wah, wal, ba, nullptr, 3 * CC, 0);

    // 2) flash attention -> pre-split y hi/lo [B,T,C]
    attn_tc_kernel<<<dim3(TT / 128, BB * HH), 256, ATTN_SMEM>>>(am);

    // 3) output projection -> d_out fp32
    tc_gemm_kernel<<<dim3(CC / 128, M / 128), 256, GEMM_SMEM>>>(
        yh, yl, wph, wpl, bp, out, CC, 1);
}